// round 11
// baseline (speedup 1.0000x reference)
#include <cuda_runtime.h>
#include <cuda_fp16.h>
#include <math.h>
#include <stdint.h>

#define NTOK 4096
#define DDIM 1024
#define NEXP 8
#define HDIM 4096
#define BKH 64
#define CONVBLKS 1024
#define SPLITK 2
#define KSLICE (HDIM / SPLITK)

// work queue layout
#define N_CONV  2048                         // w2 convert chunks
#define N_G1    8192                         // gemm1 tiles (8e x 32m x 32n)
#define N_PH1   (N_CONV + N_G1)              // 10240, conv interleaved 1-in-5
#define N_G2    4096                         // gemm2 tiles (8e x 32m x 8n x 2ksl)
#define QTOTAL  (N_PH1 + N_G2)

// ---------------- scratch ----------------
__device__ __half g_xnh[(size_t)NTOK * DDIM];
__device__ __half g_w1h[(size_t)NEXP * DDIM * HDIM];
__device__ __half g_w2h[(size_t)NEXP * HDIM * DDIM];
__device__ __half g_h[(size_t)NEXP * NTOK * HDIM];
__device__ int    g_cnt[NEXP];
__device__ float  g_psum[NEXP];
__device__ int    g_tok[NEXP * NTOK];
__device__ float  g_gate[NEXP * NTOK];
__device__ int    g_done1[NEXP * 32];        // per (e, mblk) completed gemm1 n-tiles
__device__ int    g_conv_done;
__device__ int    g_qhead;

// ---------------- helpers ----------------
__device__ __forceinline__ uint32_t smem_u32(const void* p) {
    uint32_t a;
    asm("{ .reg .u64 t; cvta.to.shared.u64 t, %1; cvt.u32.u64 %0, t; }" : "=r"(a) : "l"(p));
    return a;
}
__device__ __forceinline__ uint32_t pack_h2(float a, float b) {
    __half2 h = __floats2half2_rn(a, b);
    return *(uint32_t*)&h;
}
#define CP16(dst, src) \
    asm volatile("cp.async.cg.shared.global [%0], [%1], 16;" :: "r"(dst), "l"(src))
#define CP16Z(dst, src, bytes) \
    asm volatile("cp.async.cg.shared.global [%0], [%1], 16, %2;" :: "r"(dst), "l"(src), "r"(bytes))
#define CP_COMMIT() asm volatile("cp.async.commit_group;" ::: "memory")
#define CP_WAIT1()  asm volatile("cp.async.wait_group 1;" ::: "memory")

#define LDSM_X4(r0, r1, r2, r3, addr) \
    asm volatile("ldmatrix.sync.aligned.m8n8.x4.shared.b16 {%0,%1,%2,%3}, [%4];" \
        : "=r"(r0), "=r"(r1), "=r"(r2), "=r"(r3) : "r"(addr))
#define LDSM_X4T(r0, r1, r2, r3, addr) \
    asm volatile("ldmatrix.sync.aligned.m8n8.x4.trans.shared.b16 {%0,%1,%2,%3}, [%4];" \
        : "=r"(r0), "=r"(r1), "=r"(r2), "=r"(r3) : "r"(addr))

__device__ __forceinline__ void mma_f16(float* d, const uint32_t* a, const uint32_t* b) {
    asm volatile(
        "mma.sync.aligned.m16n8k16.row.col.f32.f16.f16.f32 "
        "{%0,%1,%2,%3}, {%4,%5,%6,%7}, {%8,%9}, {%0,%1,%2,%3};"
        : "+f"(d[0]), "+f"(d[1]), "+f"(d[2]), "+f"(d[3])
        : "r"(a[0]), "r"(a[1]), "r"(a[2]), "r"(a[3]), "r"(b[0]), "r"(b[1]));
}

#define AST 72
#define BST 136
#define ABUF_H (128 * AST)
#define BBUF_H (BKH * BST)
#define NSTAGE 3
#define SMEM_BYTES ((NSTAGE * (ABUF_H + BBUF_H)) * 2 + 512 + 128)

// ---------------- reset counters ----------------
__global__ void zero_kernel() {
    int t = threadIdx.x;
    if (t < NEXP) { g_cnt[t] = 0; g_psum[t] = 0.0f; }
    if (t < NEXP * 32) g_done1[t] = 0;
    if (t == 0) { g_conv_done = 0; g_qhead = 0; }
}

// ---------------- prep: LN + router + residual copy + w1 convert ----------------
__global__ __launch_bounds__(256) void prep_kernel(
    const float* __restrict__ x, const float* __restrict__ gamma,
    const float* __restrict__ beta, const float* __restrict__ gw,
    const float4* __restrict__ w1,
    float* __restrict__ out, float* __restrict__ probs_out)
{
    const int tid = threadIdx.x;

    if (blockIdx.x >= NTOK) {
        const int n4 = NEXP * DDIM * HDIM / 4;
        uint2* o1 = (uint2*)g_w1h;
        for (int i = (blockIdx.x - NTOK) * 256 + tid; i < n4;
             i += CONVBLKS * 256) {
            float4 v = w1[i];
            uint2 o;
            o.x = pack_h2(v.x, v.y);
            o.y = pack_h2(v.z, v.w);
            o1[i] = o;
        }
        return;
    }

    const int n = blockIdx.x;
    const int lane = tid & 31, warp = tid >> 5;

    float4 v = reinterpret_cast<const float4*>(x + (size_t)n * DDIM)[tid];
    reinterpret_cast<float4*>(out + (size_t)n * DDIM)[tid] = v;

    float s  = v.x + v.y + v.z + v.w;
    float ss = v.x * v.x + v.y * v.y + v.z * v.z + v.w * v.w;

    __shared__ float rs[8], rss[8];
    #pragma unroll
    for (int o = 16; o; o >>= 1) {
        s  += __shfl_down_sync(0xffffffffu, s, o);
        ss += __shfl_down_sync(0xffffffffu, ss, o);
    }
    if (lane == 0) { rs[warp] = s; rss[warp] = ss; }
    __syncthreads();

    __shared__ float s_mu, s_rstd;
    if (tid == 0) {
        float S = 0.f, SS = 0.f;
        #pragma unroll
        for (int i = 0; i < 8; i++) { S += rs[i]; SS += rss[i]; }
        float mu = S / (float)DDIM;
        float var = SS / (float)DDIM - mu * mu;
        s_mu = mu; s_rstd = rsqrtf(var + 1e-5f);
    }
    __syncthreads();
    const float mu = s_mu, r = s_rstd;

    float4 g4 = reinterpret_cast<const float4*>(gamma)[tid];
    float4 b4 = reinterpret_cast<const float4*>(beta)[tid];
    float xn0 = (v.x - mu) * r * g4.x + b4.x;
    float xn1 = (v.y - mu) * r * g4.y + b4.y;
    float xn2 = (v.z - mu) * r * g4.z + b4.z;
    float xn3 = (v.w - mu) * r * g4.w + b4.w;
    {
        uint2 o;
        o.x = pack_h2(xn0, xn1);
        o.y = pack_h2(xn2, xn3);
        reinterpret_cast<uint2*>(g_xnh + (size_t)n * DDIM)[tid] = o;
    }

    float lg[NEXP];
    {
        const float4* gwr = reinterpret_cast<const float4*>(gw + (size_t)tid * 4 * NEXP);
        float4 a0 = gwr[0], a1 = gwr[1];
        float4 c0 = gwr[2], c1 = gwr[3];
        float4 d0 = gwr[4], d1 = gwr[5];
        float4 e0 = gwr[6], e1 = gwr[7];
        lg[0] = xn0*a0.x + xn1*c0.x + xn2*d0.x + xn3*e0.x;
        lg[1] = xn0*a0.y + xn1*c0.y + xn2*d0.y + xn3*e0.y;
        lg[2] = xn0*a0.z + xn1*c0.z + xn2*d0.z + xn3*e0.z;
        lg[3] = xn0*a0.w + xn1*c0.w + xn2*d0.w + xn3*e0.w;
        lg[4] = xn0*a1.x + xn1*c1.x + xn2*d1.x + xn3*e1.x;
        lg[5] = xn0*a1.y + xn1*c1.y + xn2*d1.y + xn3*e1.y;
        lg[6] = xn0*a1.z + xn1*c1.z + xn2*d1.z + xn3*e1.z;
        lg[7] = xn0*a1.w + xn1*c1.w + xn2*d1.w + xn3*e1.w;
    }

    __shared__ float sl[8][NEXP];
    #pragma unroll
    for (int e = 0; e < NEXP; e++) {
        float t = lg[e];
        #pragma unroll
        for (int o = 16; o; o >>= 1) t += __shfl_down_sync(0xffffffffu, t, o);
        if (lane == 0) sl[warp][e] = t;
    }
    __syncthreads();

    if (tid == 0) {
        float logit[NEXP];
        #pragma unroll
        for (int e = 0; e < NEXP; e++) {
            float t = 0.f;
            #pragma unroll
            for (int w = 0; w < 8; w++) t += sl[w][e];
            logit[e] = t;
        }
        float mx = logit[0];
        #pragma unroll
        for (int e = 1; e < NEXP; e++) mx = fmaxf(mx, logit[e]);
        float p[NEXP], denom = 0.f;
        #pragma unroll
        for (int e = 0; e < NEXP; e++) { p[e] = expf(logit[e] - mx); denom += p[e]; }
        float inv = 1.0f / denom;
        #pragma unroll
        for (int e = 0; e < NEXP; e++) {
            p[e] *= inv;
            probs_out[(size_t)n * NEXP + e] = p[e];
            atomicAdd(&g_psum[e], p[e]);
        }
        int i1 = 0;
        #pragma unroll
        for (int e = 1; e < NEXP; e++) if (p[e] > p[i1]) i1 = e;
        int i2 = (i1 == 0) ? 1 : 0;
        #pragma unroll
        for (int e = 0; e < NEXP; e++) if (e != i1 && p[e] > p[i2]) i2 = e;
        float wsum = p[i1] + p[i2] + 1e-8f;
        float w1v = p[i1] / wsum, w2v = p[i2] / wsum;
        int r1 = atomicAdd(&g_cnt[i1], 1);
        g_tok[i1 * NTOK + r1] = n; g_gate[i1 * NTOK + r1] = w1v;
        int r2 = atomicAdd(&g_cnt[i2], 1);
        g_tok[i2 * NTOK + r2] = n; g_gate[i2 * NTOK + r2] = w2v;
    }
}

// ============ shared fp16 HMMA mainloop (proven R10 core) ============
__device__ __forceinline__ void gemm_mainloop(
    uint32_t sA, uint32_t sB,
    const __half* aptr0, const __half* aptr1, const __half* aptr2, const __half* aptr3,
    uint32_t ab0, uint32_t ab1, uint32_t ab2, uint32_t ab3,
    const __half* bptr0, const __half* bptr1, const __half* bptr2, const __half* bptr3,
    size_t b_adv,
    int NK, float acc[4][4][4])
{
    const int tid = threadIdx.x;
    const int lane = tid & 31;
    const int warp = tid >> 5;
    const int wm64 = (warp >> 2) * 64;
    const int wn32 = (warp & 3) * 32;

    const uint32_t a_soff = (uint32_t)(((tid >> 3) * AST + (tid & 7) * 8) * 2);
    const uint32_t b_soff = (uint32_t)(((tid >> 4) * BST + (tid & 15) * 8) * 2);
    const uint32_t a_rstep = (uint32_t)(32 * AST * 2);
    const uint32_t b_rstep = (uint32_t)(16 * BST * 2);

    const int lrow = (lane & 7) + 8 * ((lane >> 3) & 1);
    const int lhi  = 8 * (lane >> 4);
    uint32_t aoff[4], boff[2];
    #pragma unroll
    for (int mt = 0; mt < 4; mt++)
        aoff[mt] = (uint32_t)(((wm64 + mt * 16 + lrow) * AST + lhi) * 2);
    #pragma unroll
    for (int np = 0; np < 2; np++)
        boff[np] = (uint32_t)((lrow * BST + wn32 + np * 16 + lhi) * 2);

    const __half* ap[4] = {aptr0, aptr1, aptr2, aptr3};
    uint32_t ab[4] = {ab0, ab1, ab2, ab3};
    const __half* bp[4] = {bptr0, bptr1, bptr2, bptr3};

    #pragma unroll
    for (int st = 0; st < 2; st++) {
        uint32_t dA = sA + st * (ABUF_H * 2) + a_soff;
        uint32_t dB = sB + st * (BBUF_H * 2) + b_soff;
        #pragma unroll
        for (int i = 0; i < 4; i++) {
            CP16Z(dA + i * a_rstep, ap[i], ab[i]); ap[i] += BKH;
        }
        #pragma unroll
        for (int i = 0; i < 4; i++) {
            CP16(dB + i * b_rstep, bp[i]); bp[i] += b_adv;
        }
        CP_COMMIT();
    }

    for (int ic = 0; ic < NK; ic++) {
        CP_WAIT1();
        __syncthreads();

        if (ic + 2 < NK) {
            const int st = (ic + 2) % NSTAGE;
            uint32_t dA = sA + st * (ABUF_H * 2) + a_soff;
            uint32_t dB = sB + st * (BBUF_H * 2) + b_soff;
            #pragma unroll
            for (int i = 0; i < 4; i++) {
                CP16Z(dA + i * a_rstep, ap[i], ab[i]); ap[i] += BKH;
            }
            #pragma unroll
            for (int i = 0; i < 4; i++) {
                CP16(dB + i * b_rstep, bp[i]); bp[i] += b_adv;
            }
        }
        CP_COMMIT();

        const uint32_t sAt = sA + (ic % NSTAGE) * (ABUF_H * 2);
        const uint32_t sBt = sB + (ic % NSTAGE) * (BBUF_H * 2);
        #pragma unroll
        for (int ks = 0; ks < 4; ks++) {
            uint32_t af[4][4], bf[2][4];
            #pragma unroll
            for (int mt = 0; mt < 4; mt++)
                LDSM_X4(af[mt][0], af[mt][1], af[mt][2], af[mt][3],
                        sAt + aoff[mt] + ks * 32);
            #pragma unroll
            for (int np = 0; np < 2; np++)
                LDSM_X4T(bf[np][0], bf[np][1], bf[np][2], bf[np][3],
                         sBt + boff[np] + ks * 16 * BST * 2);
            #pragma unroll
            for (int mt = 0; mt < 4; mt++)
                #pragma unroll
                for (int nt = 0; nt < 4; nt++)
                    mma_f16(acc[mt][nt], af[mt], &bf[nt >> 1][(nt & 1) * 2]);
        }
    }
}

// ---- gemm1 tile: g_h[e, m0:m0+128, n0:n0+128] = gelu(gather(xnh)@w1h + b1) ----
__device__ void gemm1_tile(int g1, const float* __restrict__ b1, char* smem)
{
    const int e = g1 >> 10;
    const int mblk = (g1 >> 5) & 31;
    const int nt_i = g1 & 31;
    const int cnt = g_cnt[e];
    const int m0 = mblk * 128;
    if (m0 >= cnt) return;
    const int n0 = nt_i * 128;

    const uint32_t sA = smem_u32(smem);
    const uint32_t sB = sA + NSTAGE * ABUF_H * 2;
    int* s_tok = (int*)(smem + NSTAGE * (ABUF_H + BBUF_H) * 2);

    const int tid = threadIdx.x;
    if (tid < 128)
        s_tok[tid] = (m0 + tid < cnt) ? g_tok[e * NTOK + m0 + tid] : 0;
    __syncthreads();

    const int arow = tid >> 3;
    const int acol = (tid & 7) * 8;
    const __half* ap[4];
    uint32_t ab[4];
    #pragma unroll
    for (int i = 0; i < 4; i++) {
        int m = m0 + arow + 32 * i;
        bool valid = m < cnt;
        ap[i] = g_xnh + (size_t)s_tok[arow + 32 * i] * DDIM + acol;
        ab[i] = valid ? 16u : 0u;
    }
    const int brow = tid >> 4;
    const int bcol = (tid & 15) * 8;
    const __half* bp[4];
    #pragma unroll
    for (int i = 0; i < 4; i++)
        bp[i] = g_w1h + (size_t)e * DDIM * HDIM + (size_t)(brow + 16 * i) * HDIM + n0 + bcol;

    float acc[4][4][4];
    #pragma unroll
    for (int mt = 0; mt < 4; mt++)
        #pragma unroll
        for (int nt = 0; nt < 4; nt++)
            #pragma unroll
            for (int q = 0; q < 4; q++) acc[mt][nt][q] = 0.f;

    gemm_mainloop(sA, sB, ap[0], ap[1], ap[2], ap[3], ab[0], ab[1], ab[2], ab[3],
                  bp[0], bp[1], bp[2], bp[3], (size_t)BKH * HDIM,
                  DDIM / BKH, acc);

    const int lane = tid & 31;
    const int warp = tid >> 5;
    const int wm64 = (warp >> 2) * 64;
    const int wn32 = (warp & 3) * 32;
    const int gr = lane >> 2, tg = lane & 3;

    const float* b1e = b1 + (size_t)e * HDIM + n0;
    #pragma unroll
    for (int mt = 0; mt < 4; mt++) {
        #pragma unroll
        for (int half = 0; half < 2; half++) {
            int m = m0 + wm64 + mt * 16 + gr + 8 * half;
            if (m >= cnt) continue;
            __half* hrow = g_h + ((size_t)e * NTOK + m) * HDIM + n0;
            #pragma unroll
            for (int nt = 0; nt < 4; nt++) {
                int c = wn32 + nt * 8 + 2 * tg;
                float v0 = acc[mt][nt][2 * half + 0] + b1e[c];
                float v1 = acc[mt][nt][2 * half + 1] + b1e[c + 1];
                v0 = 0.5f * v0 * (1.0f + erff(v0 * 0.70710678118654752f));
                v1 = 0.5f * v1 * (1.0f + erff(v1 * 0.70710678118654752f));
                *(uint32_t*)(hrow + c) = pack_h2(v0, v1);
            }
        }
    }

    // release: all stores done -> bump producer counter
    __syncthreads();
    if (tid == 0) {
        __threadfence();
        atomicAdd(&g_done1[e * 32 + mblk], 1);
    }
}

// ---- gemm2 tile (split-K): out += gate * (g_h @ w2h + b2) ----
__device__ void gemm2_tile(int j, const float* __restrict__ b2,
                           float* __restrict__ out, char* smem)
{
    const int e = j >> 9;
    const int mblk = (j >> 4) & 31;
    const int nti = (j >> 1) & 7;
    const int ksl = j & 1;
    const int cnt = g_cnt[e];
    const int m0 = mblk * 128;
    if (m0 >= cnt) return;
    const int n0 = nti * 128;

    // wait for producers: all 32 gemm1 n-tiles of (e, mblk) and full w2 convert
    const int tid = threadIdx.x;
    if (tid == 0) {
        volatile int* dp = &g_done1[e * 32 + mblk];
        volatile int* cp = &g_conv_done;
        while (*dp < 32 || *cp < N_CONV) { }
        __threadfence();
    }
    __syncthreads();

    const uint32_t sA = smem_u32(smem);
    const uint32_t sB = sA + NSTAGE * ABUF_H * 2;

    const int arow = tid >> 3;
    const int acol = (tid & 7) * 8;
    const __half* ap[4];
    uint32_t ab[4];
    #pragma unroll
    for (int i = 0; i < 4; i++) {
        int m = m0 + arow + 32 * i;
        bool valid = m < cnt;
        ap[i] = g_h + ((size_t)e * NTOK + (valid ? m : m0)) * HDIM +
                ksl * KSLICE + acol;
        ab[i] = valid ? 16u : 0u;
    }
    const int brow = tid >> 4;
    const int bcol = (tid & 15) * 8;
    const __half* bp[4];
    #pragma unroll
    for (int i = 0; i < 4; i++)
        bp[i] = g_w2h + (size_t)e * HDIM * DDIM +
                (size_t)(ksl * KSLICE + brow + 16 * i) * DDIM + n0 + bcol;

    float acc[4][4][4];
    #pragma unroll
    for (int mt = 0; mt < 4; mt++)
        #pragma unroll
        for (int nt = 0; nt < 4; nt++)
            #pragma unroll
            for (int q = 0; q < 4; q++) acc[mt][nt][q] = 0.f;

    gemm_mainloop(sA, sB, ap[0], ap[1], ap[2], ap[3], ab[0], ab[1], ab[2], ab[3],
                  bp[0], bp[1], bp[2], bp[3], (size_t)BKH * DDIM,
                  KSLICE / BKH, acc);

    const int lane = tid & 31;
    const int warp = tid >> 5;
    const int wm64 = (warp >> 2) * 64;
    const int wn32 = (warp & 3) * 32;
    const int gr = lane >> 2, tg = lane & 3;

    const float* b2e = b2 + (size_t)e * DDIM + n0;
    const float bias_scale = (ksl == 0) ? 1.0f : 0.0f;
    #pragma unroll
    for (int mt = 0; mt < 4; mt++) {
        #pragma unroll
        for (int half = 0; half < 2; half++) {
            int m = m0 + wm64 + mt * 16 + gr + 8 * half;
            if (m >= cnt) continue;
            int token = g_tok[e * NTOK + m];
            float gate = g_gate[e * NTOK + m];
            float* orow = out + (size_t)token * DDIM + n0;
            #pragma unroll
            for (int nt = 0; nt < 4; nt++) {
                int c = wn32 + nt * 8 + 2 * tg;
                float v0 = acc[mt][nt][2 * half + 0] + bias_scale * b2e[c];
                float v1 = acc[mt][nt][2 * half + 1] + bias_scale * b2e[c + 1];
                atomicAdd(&orow[c], gate * v0);
                atomicAdd(&orow[c + 1], gate * v1);
            }
        }
    }
}

// ---- w2 convert chunk ----
__device__ void conv_tile(int cidx, const float4* __restrict__ w2)
{
    const int n4 = NEXP * HDIM * DDIM / 4;   // 8388608
    const int chunk = n4 / N_CONV;           // 4096
    const int base = cidx * chunk;
    uint2* o2 = (uint2*)g_w2h;
    for (int k = threadIdx.x; k < chunk; k += 256) {
        float4 v = w2[base + k];
        uint2 o;
        o.x = pack_h2(v.x, v.y);
        o.y = pack_h2(v.z, v.w);
        o2[base + k] = o;
    }
    __syncthreads();
    if (threadIdx.x == 0) {
        __threadfence();
        atomicAdd(&g_conv_done, 1);
    }
}

// ============ persistent fused MoE kernel ============
__global__ __launch_bounds__(256, 2) void moe_kernel(
    const float* __restrict__ b1, const float* __restrict__ b2,
    const float4* __restrict__ w2, float* __restrict__ out)
{
    extern __shared__ char smem[];
    __shared__ int s_item;

    for (;;) {
        if (threadIdx.x == 0) s_item = atomicAdd(&g_qhead, 1);
        __syncthreads();
        const int idx = s_item;
        if (idx >= QTOTAL) return;

        if (idx < N_PH1) {
            // conv interleaved 1-in-5 with gemm1 tiles
            if ((idx % 5) == 4) conv_tile(idx / 5, w2);
            else                gemm1_tile((idx / 5) * 4 + (idx % 5), b1, smem);
        } else {
            gemm2_tile(idx - N_PH1, b2, out, smem);
        }
        __syncthreads();   // protect s_item before next pop
    }
}

// ---------------- balance loss scalar ----------------
__global__ void finish_kernel(float* __restrict__ out) {
    if (threadIdx.x == 0) {
        float acc = 0.f;
        #pragma unroll
        for (int e = 0; e < NEXP; e++) acc += (float)g_cnt[e] * g_psum[e];
        out[(size_t)NTOK * DDIM] =
            0.01f * (float)NEXP * acc / ((float)NTOK * (float)NTOK);
    }
}

// ---------------- launch ----------------
extern "C" void kernel_launch(void* const* d_in, const int* in_sizes, int n_in,
                              void* d_out, int out_size)
{
    const float* x     = (const float*)d_in[0];
    const float* gamma = (const float*)d_in[1];
    const float* beta  = (const float*)d_in[2];
    const float* gw    = (const float*)d_in[3];
    const float* w1    = (const float*)d_in[4];
    const float* b1    = (const float*)d_in[5];
    const float* w2    = (const float*)d_in[6];
    const float* b2    = (const float*)d_in[7];
    float* out = (float*)d_out;

    cudaFuncSetAttribute(moe_kernel, cudaFuncAttributeMaxDynamicSharedMemorySize, SMEM_BYTES);

    // persistent grid: exactly the resident capacity (spin-safe by construction)
    int nsm = 0, occ = 0;
    cudaDeviceGetAttribute(&nsm, cudaDevAttrMultiProcessorCount, 0);
    cudaOccupancyMaxActiveBlocksPerMultiprocessor(&occ, moe_kernel, 256, SMEM_BYTES);
    if (occ < 1) occ = 1;
    if (occ > 2) occ = 2;
    int grid = nsm * occ;

    zero_kernel<<<1, 256>>>();
    prep_kernel<<<NTOK + CONVBLKS, 256>>>(x, gamma, beta, gw,
                                          (const float4*)w1,
                                          out, out + (size_t)NTOK * DDIM + 1);
    moe_kernel<<<grid, 256, SMEM_BYTES>>>(b1, b2, (const float4*)w2, out);
    finish_kernel<<<1, 32>>>(out);
}

// round 12
// speedup vs baseline: 1.0825x; 1.0825x over previous
#include <cuda_runtime.h>
#include <cuda_fp16.h>
#include <math.h>
#include <stdint.h>

#define NTOK 4096
#define DDIM 1024
#define NEXP 8
#define HDIM 4096
#define BKH 64            // k per tile (halves)
#define CONVBLKS 1024
#define SPLITK 4
#define KSLICE (HDIM / SPLITK)

// ---------------- scratch ----------------
__device__ __half g_xnh[(size_t)NTOK * DDIM];                  // normalized x, fp16
__device__ __half g_w1h[(size_t)NEXP * DDIM * HDIM];           // w1 fp16
__device__ __half g_w2h[(size_t)NEXP * HDIM * DDIM];           // w2 fp16
__device__ __half g_h[(size_t)NEXP * NTOK * HDIM];             // hidden, fp16
__device__ int    g_cnt[NEXP];
__device__ float  g_psum[NEXP];
__device__ int    g_tok[NEXP * NTOK];
__device__ float  g_gate[NEXP * NTOK];

// ---------------- helpers ----------------
__device__ __forceinline__ uint32_t smem_u32(const void* p) {
    uint32_t a;
    asm("{ .reg .u64 t; cvta.to.shared.u64 t, %1; cvt.u32.u64 %0, t; }" : "=r"(a) : "l"(p));
    return a;
}
__device__ __forceinline__ uint32_t pack_h2(float a, float b) {
    __half2 h = __floats2half2_rn(a, b);
    return *(uint32_t*)&h;
}
// .cg: L2-only path (no L1 fill) — GEMM tiles have no L1 reuse
#define CP16(dst, src) \
    asm volatile("cp.async.cg.shared.global [%0], [%1], 16;" :: "r"(dst), "l"(src))
#define CP16Z(dst, src, bytes) \
    asm volatile("cp.async.cg.shared.global [%0], [%1], 16, %2;" :: "r"(dst), "l"(src), "r"(bytes))
#define CP_COMMIT() asm volatile("cp.async.commit_group;" ::: "memory")
#define CP_WAIT1()  asm volatile("cp.async.wait_group 1;" ::: "memory")

#define LDSM_X4(r0, r1, r2, r3, addr) \
    asm volatile("ldmatrix.sync.aligned.m8n8.x4.shared.b16 {%0,%1,%2,%3}, [%4];" \
        : "=r"(r0), "=r"(r1), "=r"(r2), "=r"(r3) : "r"(addr))
#define LDSM_X4T(r0, r1, r2, r3, addr) \
    asm volatile("ldmatrix.sync.aligned.m8n8.x4.trans.shared.b16 {%0,%1,%2,%3}, [%4];" \
        : "=r"(r0), "=r"(r1), "=r"(r2), "=r"(r3) : "r"(addr))

__device__ __forceinline__ void mma_f16(float* d, const uint32_t* a, const uint32_t* b) {
    asm volatile(
        "mma.sync.aligned.m16n8k16.row.col.f32.f16.f16.f32 "
        "{%0,%1,%2,%3}, {%4,%5,%6,%7}, {%8,%9}, {%0,%1,%2,%3};"
        : "+f"(d[0]), "+f"(d[1]), "+f"(d[2]), "+f"(d[3])
        : "r"(a[0]), "r"(a[1]), "r"(a[2]), "r"(a[3]), "r"(b[0]), "r"(b[1]));
}

// smem strides in halves (stride mod 128B = 16B -> conflict-free ldmatrix)
#define AST 72
#define BST 136
#define ABUF_H (128 * AST)   // halves / stage
#define BBUF_H (BKH * BST)   // halves / stage
#define NSTAGE 3
#define SMEM_BYTES ((NSTAGE * (ABUF_H + BBUF_H)) * 2 + 512 + 128)

// ---------------- reset counters ----------------
__global__ void zero_kernel() {
    int t = threadIdx.x;
    if (t < NEXP) { g_cnt[t] = 0; g_psum[t] = 0.0f; }
}

// ---------------- merged prep: LN+router+residual copy, + w1 convert ----------
__global__ __launch_bounds__(256) void prep_kernel(
    const float* __restrict__ x, const float* __restrict__ gamma,
    const float* __restrict__ beta, const float* __restrict__ gw,
    const float4* __restrict__ w1,
    float* __restrict__ out, float* __restrict__ probs_out)
{
    const int tid = threadIdx.x;

    if (blockIdx.x >= NTOK) {
        // w1 convert only (w2 converts inside gemm1's grid)
        const int n4 = NEXP * DDIM * HDIM / 4;
        uint2* o1 = (uint2*)g_w1h;
        for (int i = (blockIdx.x - NTOK) * 256 + tid; i < n4;
             i += CONVBLKS * 256) {
            float4 v = w1[i];
            uint2 o;
            o.x = pack_h2(v.x, v.y);
            o.y = pack_h2(v.z, v.w);
            o1[i] = o;
        }
        return;
    }

    const int n = blockIdx.x;
    const int lane = tid & 31, warp = tid >> 5;

    float4 v = reinterpret_cast<const float4*>(x + (size_t)n * DDIM)[tid];
    // residual base: out = x (replaces the serialized memcpy)
    reinterpret_cast<float4*>(out + (size_t)n * DDIM)[tid] = v;

    float s  = v.x + v.y + v.z + v.w;
    float ss = v.x * v.x + v.y * v.y + v.z * v.z + v.w * v.w;

    __shared__ float rs[8], rss[8];
    #pragma unroll
    for (int o = 16; o; o >>= 1) {
        s  += __shfl_down_sync(0xffffffffu, s, o);
        ss += __shfl_down_sync(0xffffffffu, ss, o);
    }
    if (lane == 0) { rs[warp] = s; rss[warp] = ss; }
    __syncthreads();

    __shared__ float s_mu, s_rstd;
    if (tid == 0) {
        float S = 0.f, SS = 0.f;
        #pragma unroll
        for (int i = 0; i < 8; i++) { S += rs[i]; SS += rss[i]; }
        float mu = S / (float)DDIM;
        float var = SS / (float)DDIM - mu * mu;
        s_mu = mu; s_rstd = rsqrtf(var + 1e-5f);
    }
    __syncthreads();
    const float mu = s_mu, r = s_rstd;

    float4 g4 = reinterpret_cast<const float4*>(gamma)[tid];
    float4 b4 = reinterpret_cast<const float4*>(beta)[tid];
    float xn0 = (v.x - mu) * r * g4.x + b4.x;
    float xn1 = (v.y - mu) * r * g4.y + b4.y;
    float xn2 = (v.z - mu) * r * g4.z + b4.z;
    float xn3 = (v.w - mu) * r * g4.w + b4.w;
    {
        uint2 o;
        o.x = pack_h2(xn0, xn1);
        o.y = pack_h2(xn2, xn3);
        reinterpret_cast<uint2*>(g_xnh + (size_t)n * DDIM)[tid] = o;
    }

    float lg[NEXP];
    {
        const float4* gwr = reinterpret_cast<const float4*>(gw + (size_t)tid * 4 * NEXP);
        float4 a0 = gwr[0], a1 = gwr[1];
        float4 c0 = gwr[2], c1 = gwr[3];
        float4 d0 = gwr[4], d1 = gwr[5];
        float4 e0 = gwr[6], e1 = gwr[7];
        lg[0] = xn0*a0.x + xn1*c0.x + xn2*d0.x + xn3*e0.x;
        lg[1] = xn0*a0.y + xn1*c0.y + xn2*d0.y + xn3*e0.y;
        lg[2] = xn0*a0.z + xn1*c0.z + xn2*d0.z + xn3*e0.z;
        lg[3] = xn0*a0.w + xn1*c0.w + xn2*d0.w + xn3*e0.w;
        lg[4] = xn0*a1.x + xn1*c1.x + xn2*d1.x + xn3*e1.x;
        lg[5] = xn0*a1.y + xn1*c1.y + xn2*d1.y + xn3*e1.y;
        lg[6] = xn0*a1.z + xn1*c1.z + xn2*d1.z + xn3*e1.z;
        lg[7] = xn0*a1.w + xn1*c1.w + xn2*d1.w + xn3*e1.w;
    }

    __shared__ float sl[8][NEXP];
    #pragma unroll
    for (int e = 0; e < NEXP; e++) {
        float t = lg[e];
        #pragma unroll
        for (int o = 16; o; o >>= 1) t += __shfl_down_sync(0xffffffffu, t, o);
        if (lane == 0) sl[warp][e] = t;
    }
    __syncthreads();

    if (tid == 0) {
        float logit[NEXP];
        #pragma unroll
        for (int e = 0; e < NEXP; e++) {
            float t = 0.f;
            #pragma unroll
            for (int w = 0; w < 8; w++) t += sl[w][e];
            logit[e] = t;
        }
        float mx = logit[0];
        #pragma unroll
        for (int e = 1; e < NEXP; e++) mx = fmaxf(mx, logit[e]);
        float p[NEXP], denom = 0.f;
        #pragma unroll
        for (int e = 0; e < NEXP; e++) { p[e] = expf(logit[e] - mx); denom += p[e]; }
        float inv = 1.0f / denom;
        #pragma unroll
        for (int e = 0; e < NEXP; e++) {
            p[e] *= inv;
            probs_out[(size_t)n * NEXP + e] = p[e];
            atomicAdd(&g_psum[e], p[e]);
        }
        int i1 = 0;
        #pragma unroll
        for (int e = 1; e < NEXP; e++) if (p[e] > p[i1]) i1 = e;
        int i2 = (i1 == 0) ? 1 : 0;
        #pragma unroll
        for (int e = 0; e < NEXP; e++) if (e != i1 && p[e] > p[i2]) i2 = e;
        float wsum = p[i1] + p[i2] + 1e-8f;
        float w1v = p[i1] / wsum, w2v = p[i2] / wsum;
        int r1 = atomicAdd(&g_cnt[i1], 1);
        g_tok[i1 * NTOK + r1] = n; g_gate[i1 * NTOK + r1] = w1v;
        int r2 = atomicAdd(&g_cnt[i2], 1);
        g_tok[i2 * NTOK + r2] = n; g_gate[i2 * NTOK + r2] = w2v;
    }
}

// ============ fp16 HMMA GEMM core: BM=128,BN=128,BK=64, 256 threads ============
// 8 warps (2x4), warp tile 64x32, 3-stage cp.async ring, ldmatrix fragments.

__device__ __forceinline__ void gemm_mainloop(
    uint32_t sA, uint32_t sB,
    const __half* aptr0, const __half* aptr1, const __half* aptr2, const __half* aptr3,
    uint32_t ab0, uint32_t ab1, uint32_t ab2, uint32_t ab3,
    const __half* bptr0, const __half* bptr1, const __half* bptr2, const __half* bptr3,
    size_t b_adv,
    int NK, float acc[4][4][4])
{
    const int tid = threadIdx.x;
    const int lane = tid & 31;
    const int warp = tid >> 5;
    const int wm64 = (warp >> 2) * 64;
    const int wn32 = (warp & 3) * 32;

    const uint32_t a_soff = (uint32_t)(((tid >> 3) * AST + (tid & 7) * 8) * 2);
    const uint32_t b_soff = (uint32_t)(((tid >> 4) * BST + (tid & 15) * 8) * 2);
    const uint32_t a_rstep = (uint32_t)(32 * AST * 2);
    const uint32_t b_rstep = (uint32_t)(16 * BST * 2);

    const int lrow = (lane & 7) + 8 * ((lane >> 3) & 1);
    const int lhi  = 8 * (lane >> 4);
    uint32_t aoff[4], boff[2];
    #pragma unroll
    for (int mt = 0; mt < 4; mt++)
        aoff[mt] = (uint32_t)(((wm64 + mt * 16 + lrow) * AST + lhi) * 2);
    #pragma unroll
    for (int np = 0; np < 2; np++)
        boff[np] = (uint32_t)((lrow * BST + wn32 + np * 16 + lhi) * 2);

    const __half* ap[4] = {aptr0, aptr1, aptr2, aptr3};
    uint32_t ab[4] = {ab0, ab1, ab2, ab3};
    const __half* bp[4] = {bptr0, bptr1, bptr2, bptr3};

    // prologue: tiles 0 and 1
    #pragma unroll
    for (int st = 0; st < 2; st++) {
        uint32_t dA = sA + st * (ABUF_H * 2) + a_soff;
        uint32_t dB = sB + st * (BBUF_H * 2) + b_soff;
        #pragma unroll
        for (int i = 0; i < 4; i++) {
            CP16Z(dA + i * a_rstep, ap[i], ab[i]); ap[i] += BKH;
        }
        #pragma unroll
        for (int i = 0; i < 4; i++) {
            CP16(dB + i * b_rstep, bp[i]); bp[i] += b_adv;
        }
        CP_COMMIT();
    }

    for (int ic = 0; ic < NK; ic++) {
        CP_WAIT1();
        __syncthreads();

        if (ic + 2 < NK) {
            const int st = (ic + 2) % NSTAGE;
            uint32_t dA = sA + st * (ABUF_H * 2) + a_soff;
            uint32_t dB = sB + st * (BBUF_H * 2) + b_soff;
            #pragma unroll
            for (int i = 0; i < 4; i++) {
                CP16Z(dA + i * a_rstep, ap[i], ab[i]); ap[i] += BKH;
            }
            #pragma unroll
            for (int i = 0; i < 4; i++) {
                CP16(dB + i * b_rstep, bp[i]); bp[i] += b_adv;
            }
        }
        CP_COMMIT();

        const uint32_t sAt = sA + (ic % NSTAGE) * (ABUF_H * 2);
        const uint32_t sBt = sB + (ic % NSTAGE) * (BBUF_H * 2);
        #pragma unroll
        for (int ks = 0; ks < 4; ks++) {
            uint32_t af[4][4], bf[2][4];
            #pragma unroll
            for (int mt = 0; mt < 4; mt++)
                LDSM_X4(af[mt][0], af[mt][1], af[mt][2], af[mt][3],
                        sAt + aoff[mt] + ks * 32);
            #pragma unroll
            for (int np = 0; np < 2; np++)
                LDSM_X4T(bf[np][0], bf[np][1], bf[np][2], bf[np][3],
                         sBt + boff[np] + ks * 16 * BST * 2);
            #pragma unroll
            for (int mt = 0; mt < 4; mt++)
                #pragma unroll
                for (int nt = 0; nt < 4; nt++)
                    mma_f16(acc[mt][nt], af[mt], &bf[nt >> 1][(nt & 1) * 2]);
        }
    }
}

// ============ GEMM 1: g_h = gelu(gather(g_xnh) @ w1h + b1)  (+ w2 convert) ====
__global__ __launch_bounds__(256, 2) void gemm1_kernel(
    const float* __restrict__ b1, const float4* __restrict__ w2)
{
    const int tid = threadIdx.x;

    if (blockIdx.z == NEXP) {
        // w2 fp32->fp16 convert riding in gemm1's grid
        const int n4 = NEXP * HDIM * DDIM / 4;
        uint2* o2 = (uint2*)g_w2h;
        const int nblk = gridDim.x * gridDim.y;
        const int bid = blockIdx.y * gridDim.x + blockIdx.x;
        for (int i = bid * 256 + tid; i < n4; i += nblk * 256) {
            float4 v = w2[i];
            uint2 o;
            o.x = pack_h2(v.x, v.y);
            o.y = pack_h2(v.z, v.w);
            o2[i] = o;
        }
        return;
    }

    const int e = blockIdx.z;
    const int cnt = g_cnt[e];
    const int m0 = blockIdx.y * 128;
    if (m0 >= cnt) return;
    const int n0 = blockIdx.x * 128;

    extern __shared__ char smem[];
    const uint32_t sA = smem_u32(smem);
    const uint32_t sB = sA + NSTAGE * ABUF_H * 2;
    int* s_tok = (int*)(smem + NSTAGE * (ABUF_H + BBUF_H) * 2);

    if (tid < 128)
        s_tok[tid] = (m0 + tid < cnt) ? g_tok[e * NTOK + m0 + tid] : 0;
    __syncthreads();

    const int arow = tid >> 3;
    const int acol = (tid & 7) * 8;
    const __half* ap[4];
    uint32_t ab[4];
    #pragma unroll
    for (int i = 0; i < 4; i++) {
        int m = m0 + arow + 32 * i;
        bool valid = m < cnt;
        ap[i] = g_xnh + (size_t)s_tok[arow + 32 * i] * DDIM + acol;
        ab[i] = valid ? 16u : 0u;
    }
    const int brow = tid >> 4;
    const int bcol = (tid & 15) * 8;
    const __half* bp[4];
    #pragma unroll
    for (int i = 0; i < 4; i++)
        bp[i] = g_w1h + (size_t)e * DDIM * HDIM + (size_t)(brow + 16 * i) * HDIM + n0 + bcol;

    float acc[4][4][4];
    #pragma unroll
    for (int mt = 0; mt < 4; mt++)
        #pragma unroll
        for (int nt = 0; nt < 4; nt++)
            #pragma unroll
            for (int q = 0; q < 4; q++) acc[mt][nt][q] = 0.f;

    gemm_mainloop(sA, sB, ap[0], ap[1], ap[2], ap[3], ab[0], ab[1], ab[2], ab[3],
                  bp[0], bp[1], bp[2], bp[3], (size_t)BKH * HDIM,
                  DDIM / BKH, acc);

    const int lane = tid & 31;
    const int warp = tid >> 5;
    const int wm64 = (warp >> 2) * 64;
    const int wn32 = (warp & 3) * 32;
    const int gr = lane >> 2, tg = lane & 3;

    const float* b1e = b1 + (size_t)e * HDIM + n0;
    #pragma unroll
    for (int mt = 0; mt < 4; mt++) {
        #pragma unroll
        for (int half = 0; half < 2; half++) {
            int m = m0 + wm64 + mt * 16 + gr + 8 * half;
            if (m >= cnt) continue;
            __half* hrow = g_h + ((size_t)e * NTOK + m) * HDIM + n0;
            #pragma unroll
            for (int nt = 0; nt < 4; nt++) {
                int c = wn32 + nt * 8 + 2 * tg;
                float v0 = acc[mt][nt][2 * half + 0] + b1e[c];
                float v1 = acc[mt][nt][2 * half + 1] + b1e[c + 1];
                v0 = 0.5f * v0 * (1.0f + erff(v0 * 0.70710678118654752f));
                v1 = 0.5f * v1 * (1.0f + erff(v1 * 0.70710678118654752f));
                *(uint32_t*)(hrow + c) = pack_h2(v0, v1);
            }
        }
    }
}

// ============ GEMM 2 (split-K=4): out += gate * (g_h @ w2h + b2) ============
__global__ __launch_bounds__(256, 2) void gemm2_kernel(
    const float* __restrict__ b2, float* __restrict__ out)
{
    const int e = blockIdx.z >> 2;
    const int ksl = blockIdx.z & 3;
    const int cnt = g_cnt[e];
    const int m0 = blockIdx.y * 128;
    if (m0 >= cnt) return;
    const int n0 = blockIdx.x * 128;

    extern __shared__ char smem[];
    const uint32_t sA = smem_u32(smem);
    const uint32_t sB = sA + NSTAGE * ABUF_H * 2;

    const int tid = threadIdx.x;

    const int arow = tid >> 3;
    const int acol = (tid & 7) * 8;
    const __half* ap[4];
    uint32_t ab[4];
    #pragma unroll
    for (int i = 0; i < 4; i++) {
        int m = m0 + arow + 32 * i;
        bool valid = m < cnt;
        ap[i] = g_h + ((size_t)e * NTOK + (valid ? m : m0)) * HDIM +
                ksl * KSLICE + acol;
        ab[i] = valid ? 16u : 0u;
    }
    const int brow = tid >> 4;
    const int bcol = (tid & 15) * 8;
    const __half* bp[4];
    #pragma unroll
    for (int i = 0; i < 4; i++)
        bp[i] = g_w2h + (size_t)e * HDIM * DDIM +
                (size_t)(ksl * KSLICE + brow + 16 * i) * DDIM + n0 + bcol;

    float acc[4][4][4];
    #pragma unroll
    for (int mt = 0; mt < 4; mt++)
        #pragma unroll
        for (int nt = 0; nt < 4; nt++)
            #pragma unroll
            for (int q = 0; q < 4; q++) acc[mt][nt][q] = 0.f;

    gemm_mainloop(sA, sB, ap[0], ap[1], ap[2], ap[3], ab[0], ab[1], ab[2], ab[3],
                  bp[0], bp[1], bp[2], bp[3], (size_t)BKH * DDIM,
                  KSLICE / BKH, acc);

    const int lane = tid & 31;
    const int warp = tid >> 5;
    const int wm64 = (warp >> 2) * 64;
    const int wn32 = (warp & 3) * 32;
    const int gr = lane >> 2, tg = lane & 3;

    const float* b2e = b2 + (size_t)e * DDIM + n0;
    const float bias_scale = (ksl == 0) ? 1.0f : 0.0f;
    #pragma unroll
    for (int mt = 0; mt < 4; mt++) {
        #pragma unroll
        for (int half = 0; half < 2; half++) {
            int m = m0 + wm64 + mt * 16 + gr + 8 * half;
            if (m >= cnt) continue;
            int token = g_tok[e * NTOK + m];
            float gate = g_gate[e * NTOK + m];
            float* orow = out + (size_t)token * DDIM + n0;
            #pragma unroll
            for (int nt = 0; nt < 4; nt++) {
                int c = wn32 + nt * 8 + 2 * tg;
                float v0 = acc[mt][nt][2 * half + 0] + bias_scale * b2e[c];
                float v1 = acc[mt][nt][2 * half + 1] + bias_scale * b2e[c + 1];
                atomicAdd(&orow[c], gate * v0);
                atomicAdd(&orow[c + 1], gate * v1);
            }
        }
    }
}

// ---------------- balance loss scalar ----------------
__global__ void finish_kernel(float* __restrict__ out) {
    if (threadIdx.x == 0) {
        float acc = 0.f;
        #pragma unroll
        for (int e = 0; e < NEXP; e++) acc += (float)g_cnt[e] * g_psum[e];
        out[(size_t)NTOK * DDIM] =
            0.01f * (float)NEXP * acc / ((float)NTOK * (float)NTOK);
    }
}

// ---------------- launch ----------------
extern "C" void kernel_launch(void* const* d_in, const int* in_sizes, int n_in,
                              void* d_out, int out_size)
{
    const float* x     = (const float*)d_in[0];
    const float* gamma = (const float*)d_in[1];
    const float* beta  = (const float*)d_in[2];
    const float* gw    = (const float*)d_in[3];
    const float* w1    = (const float*)d_in[4];
    const float* b1    = (const float*)d_in[5];
    const float* w2    = (const float*)d_in[6];
    const float* b2    = (const float*)d_in[7];
    float* out = (float*)d_out;

    cudaFuncSetAttribute(gemm1_kernel, cudaFuncAttributeMaxDynamicSharedMemorySize, SMEM_BYTES);
    cudaFuncSetAttribute(gemm2_kernel, cudaFuncAttributeMaxDynamicSharedMemorySize, SMEM_BYTES);

    zero_kernel<<<1, 32>>>();
    prep_kernel<<<NTOK + CONVBLKS, 256>>>(x, gamma, beta, gw,
                                          (const float4*)w1,
                                          out, out + (size_t)NTOK * DDIM + 1);

    // z slice NEXP carries the w2 convert blocks
    gemm1_kernel<<<dim3(HDIM / 128, NTOK / 128, NEXP + 1), 256, SMEM_BYTES>>>(
        b1, (const float4*)w2);
    gemm2_kernel<<<dim3(DDIM / 128, NTOK / 128, NEXP * SPLITK), 256, SMEM_BYTES>>>(b2, out);
    finish_kernel<<<1, 32>>>(out);
}

// round 13
// speedup vs baseline: 1.0848x; 1.0022x over previous
#include <cuda_runtime.h>
#include <cuda_fp16.h>
#include <math.h>
#include <stdint.h>

#define NTOK 4096
#define DDIM 1024
#define NEXP 8
#define HDIM 4096
#define BKH 64            // k per tile (halves)
#define CONVBLKS 1024
#define SPLITK 2
#define KSLICE (HDIM / SPLITK)
#define EHALF 4

// ---------------- scratch ----------------
__device__ __half g_xnh[(size_t)NTOK * DDIM];                  // normalized x, fp16
__device__ __half g_w1h[(size_t)NEXP * DDIM * HDIM];           // w1 fp16
__device__ __half g_w2h[(size_t)NEXP * HDIM * DDIM];           // w2 fp16
__device__ __half g_h[(size_t)NEXP * NTOK * HDIM];             // hidden, fp16
__device__ int    g_cnt[NEXP];
__device__ float  g_psum[NEXP];
__device__ int    g_tok[NEXP * NTOK];
__device__ float  g_gate[NEXP * NTOK];

// ---------------- helpers ----------------
__device__ __forceinline__ uint32_t smem_u32(const void* p) {
    uint32_t a;
    asm("{ .reg .u64 t; cvta.to.shared.u64 t, %1; cvt.u32.u64 %0, t; }" : "=r"(a) : "l"(p));
    return a;
}
__device__ __forceinline__ uint32_t pack_h2(float a, float b) {
    __half2 h = __floats2half2_rn(a, b);
    return *(uint32_t*)&h;
}
// .cg: L2-only path (no L1 fill) — GEMM tiles have no L1 reuse
#define CP16(dst, src) \
    asm volatile("cp.async.cg.shared.global [%0], [%1], 16;" :: "r"(dst), "l"(src))
#define CP16Z(dst, src, bytes) \
    asm volatile("cp.async.cg.shared.global [%0], [%1], 16, %2;" :: "r"(dst), "l"(src), "r"(bytes))
#define CP_COMMIT() asm volatile("cp.async.commit_group;" ::: "memory")
#define CP_WAIT1()  asm volatile("cp.async.wait_group 1;" ::: "memory")

#define LDSM_X4(r0, r1, r2, r3, addr) \
    asm volatile("ldmatrix.sync.aligned.m8n8.x4.shared.b16 {%0,%1,%2,%3}, [%4];" \
        : "=r"(r0), "=r"(r1), "=r"(r2), "=r"(r3) : "r"(addr))
#define LDSM_X4T(r0, r1, r2, r3, addr) \
    asm volatile("ldmatrix.sync.aligned.m8n8.x4.trans.shared.b16 {%0,%1,%2,%3}, [%4];" \
        : "=r"(r0), "=r"(r1), "=r"(r2), "=r"(r3) : "r"(addr))

__device__ __forceinline__ void mma_f16(float* d, const uint32_t* a, const uint32_t* b) {
    asm volatile(
        "mma.sync.aligned.m16n8k16.row.col.f32.f16.f16.f32 "
        "{%0,%1,%2,%3}, {%4,%5,%6,%7}, {%8,%9}, {%0,%1,%2,%3};"
        : "+f"(d[0]), "+f"(d[1]), "+f"(d[2]), "+f"(d[3])
        : "r"(a[0]), "r"(a[1]), "r"(a[2]), "r"(a[3]), "r"(b[0]), "r"(b[1]));
}

// smem strides in halves (stride mod 128B = 16B -> conflict-free ldmatrix)
#define AST 72
#define BST 136
#define ABUF_H (128 * AST)
#define BBUF_H (BKH * BST)
#define NSTAGE 3
#define SMEM_BYTES ((NSTAGE * (ABUF_H + BBUF_H)) * 2 + 512 + 128)

// ---------------- reset counters ----------------
__global__ void zero_kernel() {
    int t = threadIdx.x;
    if (t < NEXP) { g_cnt[t] = 0; g_psum[t] = 0.0f; }
}

// ---------------- merged prep: LN+router+residual copy, + w1 convert ----------
__global__ __launch_bounds__(256) void prep_kernel(
    const float* __restrict__ x, const float* __restrict__ gamma,
    const float* __restrict__ beta, const float* __restrict__ gw,
    const float4* __restrict__ w1,
    float* __restrict__ out, float* __restrict__ probs_out)
{
    const int tid = threadIdx.x;

    if (blockIdx.x >= NTOK) {
        const int n4 = NEXP * DDIM * HDIM / 4;
        uint2* o1 = (uint2*)g_w1h;
        for (int i = (blockIdx.x - NTOK) * 256 + tid; i < n4;
             i += CONVBLKS * 256) {
            float4 v = w1[i];
            uint2 o;
            o.x = pack_h2(v.x, v.y);
            o.y = pack_h2(v.z, v.w);
            o1[i] = o;
        }
        return;
    }

    const int n = blockIdx.x;
    const int lane = tid & 31, warp = tid >> 5;

    float4 v = reinterpret_cast<const float4*>(x + (size_t)n * DDIM)[tid];
    reinterpret_cast<float4*>(out + (size_t)n * DDIM)[tid] = v;

    float s  = v.x + v.y + v.z + v.w;
    float ss = v.x * v.x + v.y * v.y + v.z * v.z + v.w * v.w;

    __shared__ float rs[8], rss[8];
    #pragma unroll
    for (int o = 16; o; o >>= 1) {
        s  += __shfl_down_sync(0xffffffffu, s, o);
        ss += __shfl_down_sync(0xffffffffu, ss, o);
    }
    if (lane == 0) { rs[warp] = s; rss[warp] = ss; }
    __syncthreads();

    __shared__ float s_mu, s_rstd;
    if (tid == 0) {
        float S = 0.f, SS = 0.f;
        #pragma unroll
        for (int i = 0; i < 8; i++) { S += rs[i]; SS += rss[i]; }
        float mu = S / (float)DDIM;
        float var = SS / (float)DDIM - mu * mu;
        s_mu = mu; s_rstd = rsqrtf(var + 1e-5f);
    }
    __syncthreads();
    const float mu = s_mu, r = s_rstd;

    float4 g4 = reinterpret_cast<const float4*>(gamma)[tid];
    float4 b4 = reinterpret_cast<const float4*>(beta)[tid];
    float xn0 = (v.x - mu) * r * g4.x + b4.x;
    float xn1 = (v.y - mu) * r * g4.y + b4.y;
    float xn2 = (v.z - mu) * r * g4.z + b4.z;
    float xn3 = (v.w - mu) * r * g4.w + b4.w;
    {
        uint2 o;
        o.x = pack_h2(xn0, xn1);
        o.y = pack_h2(xn2, xn3);
        reinterpret_cast<uint2*>(g_xnh + (size_t)n * DDIM)[tid] = o;
    }

    float lg[NEXP];
    {
        const float4* gwr = reinterpret_cast<const float4*>(gw + (size_t)tid * 4 * NEXP);
        float4 a0 = gwr[0], a1 = gwr[1];
        float4 c0 = gwr[2], c1 = gwr[3];
        float4 d0 = gwr[4], d1 = gwr[5];
        float4 e0 = gwr[6], e1 = gwr[7];
        lg[0] = xn0*a0.x + xn1*c0.x + xn2*d0.x + xn3*e0.x;
        lg[1] = xn0*a0.y + xn1*c0.y + xn2*d0.y + xn3*e0.y;
        lg[2] = xn0*a0.z + xn1*c0.z + xn2*d0.z + xn3*e0.z;
        lg[3] = xn0*a0.w + xn1*c0.w + xn2*d0.w + xn3*e0.w;
        lg[4] = xn0*a1.x + xn1*c1.x + xn2*d1.x + xn3*e1.x;
        lg[5] = xn0*a1.y + xn1*c1.y + xn2*d1.y + xn3*e1.y;
        lg[6] = xn0*a1.z + xn1*c1.z + xn2*d1.z + xn3*e1.z;
        lg[7] = xn0*a1.w + xn1*c1.w + xn2*d1.w + xn3*e1.w;
    }

    __shared__ float sl[8][NEXP];
    #pragma unroll
    for (int e = 0; e < NEXP; e++) {
        float t = lg[e];
        #pragma unroll
        for (int o = 16; o; o >>= 1) t += __shfl_down_sync(0xffffffffu, t, o);
        if (lane == 0) sl[warp][e] = t;
    }
    __syncthreads();

    if (tid == 0) {
        float logit[NEXP];
        #pragma unroll
        for (int e = 0; e < NEXP; e++) {
            float t = 0.f;
            #pragma unroll
            for (int w = 0; w < 8; w++) t += sl[w][e];
            logit[e] = t;
        }
        float mx = logit[0];
        #pragma unroll
        for (int e = 1; e < NEXP; e++) mx = fmaxf(mx, logit[e]);
        float p[NEXP], denom = 0.f;
        #pragma unroll
        for (int e = 0; e < NEXP; e++) { p[e] = expf(logit[e] - mx); denom += p[e]; }
        float inv = 1.0f / denom;
        #pragma unroll
        for (int e = 0; e < NEXP; e++) {
            p[e] *= inv;
            probs_out[(size_t)n * NEXP + e] = p[e];
            atomicAdd(&g_psum[e], p[e]);
        }
        int i1 = 0;
        #pragma unroll
        for (int e = 1; e < NEXP; e++) if (p[e] > p[i1]) i1 = e;
        int i2 = (i1 == 0) ? 1 : 0;
        #pragma unroll
        for (int e = 0; e < NEXP; e++) if (e != i1 && p[e] > p[i2]) i2 = e;
        float wsum = p[i1] + p[i2] + 1e-8f;
        float w1v = p[i1] / wsum, w2v = p[i2] / wsum;
        int r1 = atomicAdd(&g_cnt[i1], 1);
        g_tok[i1 * NTOK + r1] = n; g_gate[i1 * NTOK + r1] = w1v;
        int r2 = atomicAdd(&g_cnt[i2], 1);
        g_tok[i2 * NTOK + r2] = n; g_gate[i2 * NTOK + r2] = w2v;
    }
}

// ============ fp16 HMMA GEMM core (R10 champion, unchanged) ============
__device__ __forceinline__ void gemm_mainloop(
    uint32_t sA, uint32_t sB,
    const __half* aptr0, const __half* aptr1, const __half* aptr2, const __half* aptr3,
    uint32_t ab0, uint32_t ab1, uint32_t ab2, uint32_t ab3,
    const __half* bptr0, const __half* bptr1, const __half* bptr2, const __half* bptr3,
    size_t b_adv,
    int NK, float acc[4][4][4])
{
    const int tid = threadIdx.x;
    const int lane = tid & 31;
    const int warp = tid >> 5;
    const int wm64 = (warp >> 2) * 64;
    const int wn32 = (warp & 3) * 32;

    const uint32_t a_soff = (uint32_t)(((tid >> 3) * AST + (tid & 7) * 8) * 2);
    const uint32_t b_soff = (uint32_t)(((tid >> 4) * BST + (tid & 15) * 8) * 2);
    const uint32_t a_rstep = (uint32_t)(32 * AST * 2);
    const uint32_t b_rstep = (uint32_t)(16 * BST * 2);

    const int lrow = (lane & 7) + 8 * ((lane >> 3) & 1);
    const int lhi  = 8 * (lane >> 4);
    uint32_t aoff[4], boff[2];
    #pragma unroll
    for (int mt = 0; mt < 4; mt++)
        aoff[mt] = (uint32_t)(((wm64 + mt * 16 + lrow) * AST + lhi) * 2);
    #pragma unroll
    for (int np = 0; np < 2; np++)
        boff[np] = (uint32_t)((lrow * BST + wn32 + np * 16 + lhi) * 2);

    const __half* ap[4] = {aptr0, aptr1, aptr2, aptr3};
    uint32_t ab[4] = {ab0, ab1, ab2, ab3};
    const __half* bp[4] = {bptr0, bptr1, bptr2, bptr3};

    #pragma unroll
    for (int st = 0; st < 2; st++) {
        uint32_t dA = sA + st * (ABUF_H * 2) + a_soff;
        uint32_t dB = sB + st * (BBUF_H * 2) + b_soff;
        #pragma unroll
        for (int i = 0; i < 4; i++) {
            CP16Z(dA + i * a_rstep, ap[i], ab[i]); ap[i] += BKH;
        }
        #pragma unroll
        for (int i = 0; i < 4; i++) {
            CP16(dB + i * b_rstep, bp[i]); bp[i] += b_adv;
        }
        CP_COMMIT();
    }

    for (int ic = 0; ic < NK; ic++) {
        CP_WAIT1();
        __syncthreads();

        if (ic + 2 < NK) {
            const int st = (ic + 2) % NSTAGE;
            uint32_t dA = sA + st * (ABUF_H * 2) + a_soff;
            uint32_t dB = sB + st * (BBUF_H * 2) + b_soff;
            #pragma unroll
            for (int i = 0; i < 4; i++) {
                CP16Z(dA + i * a_rstep, ap[i], ab[i]); ap[i] += BKH;
            }
            #pragma unroll
            for (int i = 0; i < 4; i++) {
                CP16(dB + i * b_rstep, bp[i]); bp[i] += b_adv;
            }
        }
        CP_COMMIT();

        const uint32_t sAt = sA + (ic % NSTAGE) * (ABUF_H * 2);
        const uint32_t sBt = sB + (ic % NSTAGE) * (BBUF_H * 2);
        #pragma unroll
        for (int ks = 0; ks < 4; ks++) {
            uint32_t af[4][4], bf[2][4];
            #pragma unroll
            for (int mt = 0; mt < 4; mt++)
                LDSM_X4(af[mt][0], af[mt][1], af[mt][2], af[mt][3],
                        sAt + aoff[mt] + ks * 32);
            #pragma unroll
            for (int np = 0; np < 2; np++)
                LDSM_X4T(bf[np][0], bf[np][1], bf[np][2], bf[np][3],
                         sBt + boff[np] + ks * 16 * BST * 2);
            #pragma unroll
            for (int mt = 0; mt < 4; mt++)
                #pragma unroll
                for (int nt = 0; nt < 4; nt++)
                    mma_f16(acc[mt][nt], af[mt], &bf[nt >> 1][(nt & 1) * 2]);
        }
    }
}

// ============ GEMM 1 (expert half): h = gelu(gather @ w1h + b1), opt. rider ====
__global__ __launch_bounds__(256, 2) void gemm1_kernel(
    const float* __restrict__ b1, const float4* __restrict__ w2,
    int e_base, int rider)
{
    const int tid = threadIdx.x;

    if (rider && blockIdx.z == EHALF) {
        // w2 fp32->fp16 convert riding in gemm1a's grid
        const int n4 = NEXP * HDIM * DDIM / 4;
        uint2* o2 = (uint2*)g_w2h;
        const int nblk = gridDim.x * gridDim.y;
        const int bid = blockIdx.y * gridDim.x + blockIdx.x;
        for (int i = bid * 256 + tid; i < n4; i += nblk * 256) {
            float4 v = w2[i];
            uint2 o;
            o.x = pack_h2(v.x, v.y);
            o.y = pack_h2(v.z, v.w);
            o2[i] = o;
        }
        return;
    }

    const int e = e_base + blockIdx.z;
    const int cnt = g_cnt[e];
    const int m0 = blockIdx.y * 128;
    if (m0 >= cnt) return;
    const int n0 = blockIdx.x * 128;

    extern __shared__ char smem[];
    const uint32_t sA = smem_u32(smem);
    const uint32_t sB = sA + NSTAGE * ABUF_H * 2;
    int* s_tok = (int*)(smem + NSTAGE * (ABUF_H + BBUF_H) * 2);

    if (tid < 128)
        s_tok[tid] = (m0 + tid < cnt) ? g_tok[e * NTOK + m0 + tid] : 0;
    __syncthreads();

    const int arow = tid >> 3;
    const int acol = (tid & 7) * 8;
    const __half* ap[4];
    uint32_t ab[4];
    #pragma unroll
    for (int i = 0; i < 4; i++) {
        int m = m0 + arow + 32 * i;
        bool valid = m < cnt;
        ap[i] = g_xnh + (size_t)s_tok[arow + 32 * i] * DDIM + acol;
        ab[i] = valid ? 16u : 0u;
    }
    const int brow = tid >> 4;
    const int bcol = (tid & 15) * 8;
    const __half* bp[4];
    #pragma unroll
    for (int i = 0; i < 4; i++)
        bp[i] = g_w1h + (size_t)e * DDIM * HDIM + (size_t)(brow + 16 * i) * HDIM + n0 + bcol;

    float acc[4][4][4];
    #pragma unroll
    for (int mt = 0; mt < 4; mt++)
        #pragma unroll
        for (int nt = 0; nt < 4; nt++)
            #pragma unroll
            for (int q = 0; q < 4; q++) acc[mt][nt][q] = 0.f;

    gemm_mainloop(sA, sB, ap[0], ap[1], ap[2], ap[3], ab[0], ab[1], ab[2], ab[3],
                  bp[0], bp[1], bp[2], bp[3], (size_t)BKH * HDIM,
                  DDIM / BKH, acc);

    const int lane = tid & 31;
    const int warp = tid >> 5;
    const int wm64 = (warp >> 2) * 64;
    const int wn32 = (warp & 3) * 32;
    const int gr = lane >> 2, tg = lane & 3;

    const float* b1e = b1 + (size_t)e * HDIM + n0;
    #pragma unroll
    for (int mt = 0; mt < 4; mt++) {
        #pragma unroll
        for (int half = 0; half < 2; half++) {
            int m = m0 + wm64 + mt * 16 + gr + 8 * half;
            if (m >= cnt) continue;
            __half* hrow = g_h + ((size_t)e * NTOK + m) * HDIM + n0;
            #pragma unroll
            for (int nt = 0; nt < 4; nt++) {
                int c = wn32 + nt * 8 + 2 * tg;
                float v0 = acc[mt][nt][2 * half + 0] + b1e[c];
                float v1 = acc[mt][nt][2 * half + 1] + b1e[c + 1];
                v0 = 0.5f * v0 * (1.0f + erff(v0 * 0.70710678118654752f));
                v1 = 0.5f * v1 * (1.0f + erff(v1 * 0.70710678118654752f));
                *(uint32_t*)(hrow + c) = pack_h2(v0, v1);
            }
        }
    }
}

// ============ GEMM 2 (expert half, split-K=2): out += gate*(h @ w2h + b2) =====
__global__ __launch_bounds__(256, 2) void gemm2_kernel(
    const float* __restrict__ b2, float* __restrict__ out, int e_base)
{
    const int e = e_base + (blockIdx.z >> 1);
    const int ksl = blockIdx.z & 1;
    const int cnt = g_cnt[e];
    const int m0 = blockIdx.y * 128;
    if (m0 >= cnt) return;
    const int n0 = blockIdx.x * 128;

    extern __shared__ char smem[];
    const uint32_t sA = smem_u32(smem);
    const uint32_t sB = sA + NSTAGE * ABUF_H * 2;

    const int tid = threadIdx.x;

    const int arow = tid >> 3;
    const int acol = (tid & 7) * 8;
    const __half* ap[4];
    uint32_t ab[4];
    #pragma unroll
    for (int i = 0; i < 4; i++) {
        int m = m0 + arow + 32 * i;
        bool valid = m < cnt;
        ap[i] = g_h + ((size_t)e * NTOK + (valid ? m : m0)) * HDIM +
                ksl * KSLICE + acol;
        ab[i] = valid ? 16u : 0u;
    }
    const int brow = tid >> 4;
    const int bcol = (tid & 15) * 8;
    const __half* bp[4];
    #pragma unroll
    for (int i = 0; i < 4; i++)
        bp[i] = g_w2h + (size_t)e * HDIM * DDIM +
                (size_t)(ksl * KSLICE + brow + 16 * i) * DDIM + n0 + bcol;

    float acc[4][4][4];
    #pragma unroll
    for (int mt = 0; mt < 4; mt++)
        #pragma unroll
        for (int nt = 0; nt < 4; nt++)
            #pragma unroll
            for (int q = 0; q < 4; q++) acc[mt][nt][q] = 0.f;

    gemm_mainloop(sA, sB, ap[0], ap[1], ap[2], ap[3], ab[0], ab[1], ab[2], ab[3],
                  bp[0], bp[1], bp[2], bp[3], (size_t)BKH * DDIM,
                  KSLICE / BKH, acc);

    const int lane = tid & 31;
    const int warp = tid >> 5;
    const int wm64 = (warp >> 2) * 64;
    const int wn32 = (warp & 3) * 32;
    const int gr = lane >> 2, tg = lane & 3;

    const float* b2e = b2 + (size_t)e * DDIM + n0;
    const float bias_scale = (ksl == 0) ? 1.0f : 0.0f;
    #pragma unroll
    for (int mt = 0; mt < 4; mt++) {
        #pragma unroll
        for (int half = 0; half < 2; half++) {
            int m = m0 + wm64 + mt * 16 + gr + 8 * half;
            if (m >= cnt) continue;
            int token = g_tok[e * NTOK + m];
            float gate = g_gate[e * NTOK + m];
            float* orow = out + (size_t)token * DDIM + n0;
            #pragma unroll
            for (int nt = 0; nt < 4; nt++) {
                int c = wn32 + nt * 8 + 2 * tg;
                float v0 = acc[mt][nt][2 * half + 0] + bias_scale * b2e[c];
                float v1 = acc[mt][nt][2 * half + 1] + bias_scale * b2e[c + 1];
                atomicAdd(&orow[c], gate * v0);
                atomicAdd(&orow[c + 1], gate * v1);
            }
        }
    }
}

// ---------------- balance loss scalar ----------------
__global__ void finish_kernel(float* __restrict__ out) {
    if (threadIdx.x == 0) {
        float acc = 0.f;
        #pragma unroll
        for (int e = 0; e < NEXP; e++) acc += (float)g_cnt[e] * g_psum[e];
        out[(size_t)NTOK * DDIM] =
            0.01f * (float)NEXP * acc / ((float)NTOK * (float)NTOK);
    }
}

// ---------------- launch ----------------
extern "C" void kernel_launch(void* const* d_in, const int* in_sizes, int n_in,
                              void* d_out, int out_size)
{
    const float* x     = (const float*)d_in[0];
    const float* gamma = (const float*)d_in[1];
    const float* beta  = (const float*)d_in[2];
    const float* gw    = (const float*)d_in[3];
    const float* w1    = (const float*)d_in[4];
    const float* b1    = (const float*)d_in[5];
    const float* w2    = (const float*)d_in[6];
    const float* b2    = (const float*)d_in[7];
    float* out = (float*)d_out;

    // one-time stream/event setup (first call is the uncaptured correctness run)
    static cudaStream_t s1 = nullptr;
    static cudaEvent_t ev_a, ev_b, ev_done;
    if (s1 == nullptr) {
        cudaStreamCreateWithFlags(&s1, cudaStreamNonBlocking);
        cudaEventCreateWithFlags(&ev_a, cudaEventDisableTiming);
        cudaEventCreateWithFlags(&ev_b, cudaEventDisableTiming);
        cudaEventCreateWithFlags(&ev_done, cudaEventDisableTiming);
        cudaFuncSetAttribute(gemm1_kernel, cudaFuncAttributeMaxDynamicSharedMemorySize, SMEM_BYTES);
        cudaFuncSetAttribute(gemm2_kernel, cudaFuncAttributeMaxDynamicSharedMemorySize, SMEM_BYTES);
    }

    zero_kernel<<<1, 32>>>();
    prep_kernel<<<NTOK + CONVBLKS, 256>>>(x, gamma, beta, gw,
                                          (const float4*)w1,
                                          out, out + (size_t)NTOK * DDIM + 1);

    // gemm1a: experts 0..3 + w2-convert rider (z slice EHALF)
    gemm1_kernel<<<dim3(HDIM / 128, NTOK / 128, EHALF + 1), 256, SMEM_BYTES>>>(
        b1, (const float4*)w2, 0, 1);
    cudaEventRecord(ev_a, 0);
    // gemm1b: experts 4..7
    gemm1_kernel<<<dim3(HDIM / 128, NTOK / 128, EHALF), 256, SMEM_BYTES>>>(
        b1, (const float4*)w2, EHALF, 0);
    cudaEventRecord(ev_b, 0);

    // s1: gemm2a (experts 0..3) overlaps gemm1b's drain
    cudaStreamWaitEvent(s1, ev_a, 0);
    gemm2_kernel<<<dim3(DDIM / 128, NTOK / 128, EHALF * SPLITK), 256, SMEM_BYTES, s1>>>(
        b2, out, 0);
    cudaStreamWaitEvent(s1, ev_b, 0);
    gemm2_kernel<<<dim3(DDIM / 128, NTOK / 128, EHALF * SPLITK), 256, SMEM_BYTES, s1>>>(
        b2, out, EHALF);
    cudaEventRecord(ev_done, s1);

    cudaStreamWaitEvent(0, ev_done, 0);
    finish_kernel<<<1, 32>>>(out);
}

// round 14
// speedup vs baseline: 1.1042x; 1.0179x over previous
#include <cuda_runtime.h>
#include <cuda_fp16.h>
#include <math.h>
#include <stdint.h>

#define NTOK 4096
#define DDIM 1024
#define NEXP 8
#define HDIM 4096
#define BKH 64            // k per tile (halves)
#define CONVBLKS 1024
#define SPLITK 2
#define KSLICE (HDIM / SPLITK)

// ---------------- scratch ----------------
__device__ __half g_xnh[(size_t)NTOK * DDIM];                  // normalized x, fp16
__device__ __half g_w1h[(size_t)NEXP * DDIM * HDIM];           // w1 fp16
__device__ __half g_w2h[(size_t)NEXP * HDIM * DDIM];           // w2 fp16
__device__ __half g_h[(size_t)NEXP * NTOK * HDIM];             // hidden, fp16
__device__ int    g_cnt[NEXP];
__device__ float  g_psum[NEXP];
__device__ int    g_tok[NEXP * NTOK];
__device__ float  g_gate[NEXP * NTOK];
__device__ int    g_g2done;                                    // gemm2 completion counter

// ---------------- helpers ----------------
__device__ __forceinline__ uint32_t smem_u32(const void* p) {
    uint32_t a;
    asm("{ .reg .u64 t; cvta.to.shared.u64 t, %1; cvt.u32.u64 %0, t; }" : "=r"(a) : "l"(p));
    return a;
}
__device__ __forceinline__ uint32_t pack_h2(float a, float b) {
    __half2 h = __floats2half2_rn(a, b);
    return *(uint32_t*)&h;
}
// .cg: L2-only path (no L1 fill) — GEMM tiles have no L1 reuse
#define CP16(dst, src) \
    asm volatile("cp.async.cg.shared.global [%0], [%1], 16;" :: "r"(dst), "l"(src))
#define CP16Z(dst, src, bytes) \
    asm volatile("cp.async.cg.shared.global [%0], [%1], 16, %2;" :: "r"(dst), "l"(src), "r"(bytes))
#define CP_COMMIT() asm volatile("cp.async.commit_group;" ::: "memory")
#define CP_WAIT1()  asm volatile("cp.async.wait_group 1;" ::: "memory")

#define LDSM_X4(r0, r1, r2, r3, addr) \
    asm volatile("ldmatrix.sync.aligned.m8n8.x4.shared.b16 {%0,%1,%2,%3}, [%4];" \
        : "=r"(r0), "=r"(r1), "=r"(r2), "=r"(r3) : "r"(addr))
#define LDSM_X4T(r0, r1, r2, r3, addr) \
    asm volatile("ldmatrix.sync.aligned.m8n8.x4.trans.shared.b16 {%0,%1,%2,%3}, [%4];" \
        : "=r"(r0), "=r"(r1), "=r"(r2), "=r"(r3) : "r"(addr))

__device__ __forceinline__ void mma_f16(float* d, const uint32_t* a, const uint32_t* b) {
    asm volatile(
        "mma.sync.aligned.m16n8k16.row.col.f32.f16.f16.f32 "
        "{%0,%1,%2,%3}, {%4,%5,%6,%7}, {%8,%9}, {%0,%1,%2,%3};"
        : "+f"(d[0]), "+f"(d[1]), "+f"(d[2]), "+f"(d[3])
        : "r"(a[0]), "r"(a[1]), "r"(a[2]), "r"(a[3]), "r"(b[0]), "r"(b[1]));
}

// smem strides in halves (stride mod 128B = 16B -> conflict-free ldmatrix)
#define AST 72
#define BST 136
#define ABUF_H (128 * AST)   // halves / stage
#define BBUF_H (BKH * BST)   // halves / stage
#define NSTAGE 3
#define SMEM_BYTES ((NSTAGE * (ABUF_H + BBUF_H)) * 2 + 1024 + 128)

// ---------------- reset counters ----------------
__global__ void zero_kernel() {
    int t = threadIdx.x;
    if (t < NEXP) { g_cnt[t] = 0; g_psum[t] = 0.0f; }
    if (t == 0) g_g2done = 0;
}

// ---------------- merged prep: LN+router+residual copy, + w1 convert ----------
__global__ __launch_bounds__(256) void prep_kernel(
    const float* __restrict__ x, const float* __restrict__ gamma,
    const float* __restrict__ beta, const float* __restrict__ gw,
    const float4* __restrict__ w1,
    float* __restrict__ out, float* __restrict__ probs_out)
{
    const int tid = threadIdx.x;

    if (blockIdx.x >= NTOK) {
        const int n4 = NEXP * DDIM * HDIM / 4;
        uint2* o1 = (uint2*)g_w1h;
        for (int i = (blockIdx.x - NTOK) * 256 + tid; i < n4;
             i += CONVBLKS * 256) {
            float4 v = w1[i];
            uint2 o;
            o.x = pack_h2(v.x, v.y);
            o.y = pack_h2(v.z, v.w);
            o1[i] = o;
        }
        return;
    }

    const int n = blockIdx.x;
    const int lane = tid & 31, warp = tid >> 5;

    float4 v = reinterpret_cast<const float4*>(x + (size_t)n * DDIM)[tid];
    // residual base: out = x
    reinterpret_cast<float4*>(out + (size_t)n * DDIM)[tid] = v;

    float s  = v.x + v.y + v.z + v.w;
    float ss = v.x * v.x + v.y * v.y + v.z * v.z + v.w * v.w;

    __shared__ float rs[8], rss[8];
    #pragma unroll
    for (int o = 16; o; o >>= 1) {
        s  += __shfl_down_sync(0xffffffffu, s, o);
        ss += __shfl_down_sync(0xffffffffu, ss, o);
    }
    if (lane == 0) { rs[warp] = s; rss[warp] = ss; }
    __syncthreads();

    __shared__ float s_mu, s_rstd;
    if (tid == 0) {
        float S = 0.f, SS = 0.f;
        #pragma unroll
        for (int i = 0; i < 8; i++) { S += rs[i]; SS += rss[i]; }
        float mu = S / (float)DDIM;
        float var = SS / (float)DDIM - mu * mu;
        s_mu = mu; s_rstd = rsqrtf(var + 1e-5f);
    }
    __syncthreads();
    const float mu = s_mu, r = s_rstd;

    float4 g4 = reinterpret_cast<const float4*>(gamma)[tid];
    float4 b4 = reinterpret_cast<const float4*>(beta)[tid];
    float xn0 = (v.x - mu) * r * g4.x + b4.x;
    float xn1 = (v.y - mu) * r * g4.y + b4.y;
    float xn2 = (v.z - mu) * r * g4.z + b4.z;
    float xn3 = (v.w - mu) * r * g4.w + b4.w;
    {
        uint2 o;
        o.x = pack_h2(xn0, xn1);
        o.y = pack_h2(xn2, xn3);
        reinterpret_cast<uint2*>(g_xnh + (size_t)n * DDIM)[tid] = o;
    }

    float lg[NEXP];
    {
        const float4* gwr = reinterpret_cast<const float4*>(gw + (size_t)tid * 4 * NEXP);
        float4 a0 = gwr[0], a1 = gwr[1];
        float4 c0 = gwr[2], c1 = gwr[3];
        float4 d0 = gwr[4], d1 = gwr[5];
        float4 e0 = gwr[6], e1 = gwr[7];
        lg[0] = xn0*a0.x + xn1*c0.x + xn2*d0.x + xn3*e0.x;
        lg[1] = xn0*a0.y + xn1*c0.y + xn2*d0.y + xn3*e0.y;
        lg[2] = xn0*a0.z + xn1*c0.z + xn2*d0.z + xn3*e0.z;
        lg[3] = xn0*a0.w + xn1*c0.w + xn2*d0.w + xn3*e0.w;
        lg[4] = xn0*a1.x + xn1*c1.x + xn2*d1.x + xn3*e1.x;
        lg[5] = xn0*a1.y + xn1*c1.y + xn2*d1.y + xn3*e1.y;
        lg[6] = xn0*a1.z + xn1*c1.z + xn2*d1.z + xn3*e1.z;
        lg[7] = xn0*a1.w + xn1*c1.w + xn2*d1.w + xn3*e1.w;
    }

    __shared__ float sl[8][NEXP];
    #pragma unroll
    for (int e = 0; e < NEXP; e++) {
        float t = lg[e];
        #pragma unroll
        for (int o = 16; o; o >>= 1) t += __shfl_down_sync(0xffffffffu, t, o);
        if (lane == 0) sl[warp][e] = t;
    }
    __syncthreads();

    if (tid == 0) {
        float logit[NEXP];
        #pragma unroll
        for (int e = 0; e < NEXP; e++) {
            float t = 0.f;
            #pragma unroll
            for (int w = 0; w < 8; w++) t += sl[w][e];
            logit[e] = t;
        }
        float mx = logit[0];
        #pragma unroll
        for (int e = 1; e < NEXP; e++) mx = fmaxf(mx, logit[e]);
        float p[NEXP], denom = 0.f;
        #pragma unroll
        for (int e = 0; e < NEXP; e++) { p[e] = expf(logit[e] - mx); denom += p[e]; }
        float inv = 1.0f / denom;
        #pragma unroll
        for (int e = 0; e < NEXP; e++) {
            p[e] *= inv;
            probs_out[(size_t)n * NEXP + e] = p[e];
            atomicAdd(&g_psum[e], p[e]);
        }
        int i1 = 0;
        #pragma unroll
        for (int e = 1; e < NEXP; e++) if (p[e] > p[i1]) i1 = e;
        int i2 = (i1 == 0) ? 1 : 0;
        #pragma unroll
        for (int e = 0; e < NEXP; e++) if (e != i1 && p[e] > p[i2]) i2 = e;
        float wsum = p[i1] + p[i2] + 1e-8f;
        float w1v = p[i1] / wsum, w2v = p[i2] / wsum;
        int r1 = atomicAdd(&g_cnt[i1], 1);
        g_tok[i1 * NTOK + r1] = n; g_gate[i1 * NTOK + r1] = w1v;
        int r2 = atomicAdd(&g_cnt[i2], 1);
        g_tok[i2 * NTOK + r2] = n; g_gate[i2 * NTOK + r2] = w2v;
    }
}

// ============ fp16 HMMA GEMM core: BM=128,BN=128,BK=64, 256 threads ============
// 8 warps (2x4), warp tile 64x32, 3-stage cp.async ring, ldmatrix fragments.

__device__ __forceinline__ void gemm_mainloop(
    uint32_t sA, uint32_t sB,
    const __half* aptr0, const __half* aptr1, const __half* aptr2, const __half* aptr3,
    uint32_t ab0, uint32_t ab1, uint32_t ab2, uint32_t ab3,
    const __half* bptr0, const __half* bptr1, const __half* bptr2, const __half* bptr3,
    size_t b_adv,
    int NK, float acc[4][4][4])
{
    const int tid = threadIdx.x;
    const int lane = tid & 31;
    const int warp = tid >> 5;
    const int wm64 = (warp >> 2) * 64;
    const int wn32 = (warp & 3) * 32;

    const uint32_t a_soff = (uint32_t)(((tid >> 3) * AST + (tid & 7) * 8) * 2);
    const uint32_t b_soff = (uint32_t)(((tid >> 4) * BST + (tid & 15) * 8) * 2);
    const uint32_t a_rstep = (uint32_t)(32 * AST * 2);
    const uint32_t b_rstep = (uint32_t)(16 * BST * 2);

    const int lrow = (lane & 7) + 8 * ((lane >> 3) & 1);
    const int lhi  = 8 * (lane >> 4);
    uint32_t aoff[4], boff[2];
    #pragma unroll
    for (int mt = 0; mt < 4; mt++)
        aoff[mt] = (uint32_t)(((wm64 + mt * 16 + lrow) * AST + lhi) * 2);
    #pragma unroll
    for (int np = 0; np < 2; np++)
        boff[np] = (uint32_t)((lrow * BST + wn32 + np * 16 + lhi) * 2);

    const __half* ap[4] = {aptr0, aptr1, aptr2, aptr3};
    uint32_t ab[4] = {ab0, ab1, ab2, ab3};
    const __half* bp[4] = {bptr0, bptr1, bptr2, bptr3};

    // prologue: tiles 0 and 1
    #pragma unroll
    for (int st = 0; st < 2; st++) {
        uint32_t dA = sA + st * (ABUF_H * 2) + a_soff;
        uint32_t dB = sB + st * (BBUF_H * 2) + b_soff;
        #pragma unroll
        for (int i = 0; i < 4; i++) {
            CP16Z(dA + i * a_rstep, ap[i], ab[i]); ap[i] += BKH;
        }
        #pragma unroll
        for (int i = 0; i < 4; i++) {
            CP16(dB + i * b_rstep, bp[i]); bp[i] += b_adv;
        }
        CP_COMMIT();
    }

    for (int ic = 0; ic < NK; ic++) {
        CP_WAIT1();
        __syncthreads();

        if (ic + 2 < NK) {
            const int st = (ic + 2) % NSTAGE;
            uint32_t dA = sA + st * (ABUF_H * 2) + a_soff;
            uint32_t dB = sB + st * (BBUF_H * 2) + b_soff;
            #pragma unroll
            for (int i = 0; i < 4; i++) {
                CP16Z(dA + i * a_rstep, ap[i], ab[i]); ap[i] += BKH;
            }
            #pragma unroll
            for (int i = 0; i < 4; i++) {
                CP16(dB + i * b_rstep, bp[i]); bp[i] += b_adv;
            }
        }
        CP_COMMIT();

        const uint32_t sAt = sA + (ic % NSTAGE) * (ABUF_H * 2);
        const uint32_t sBt = sB + (ic % NSTAGE) * (BBUF_H * 2);
        #pragma unroll
        for (int ks = 0; ks < 4; ks++) {
            uint32_t af[4][4], bf[2][4];
            #pragma unroll
            for (int mt = 0; mt < 4; mt++)
                LDSM_X4(af[mt][0], af[mt][1], af[mt][2], af[mt][3],
                        sAt + aoff[mt] + ks * 32);
            #pragma unroll
            for (int np = 0; np < 2; np++)
                LDSM_X4T(bf[np][0], bf[np][1], bf[np][2], bf[np][3],
                         sBt + boff[np] + ks * 16 * BST * 2);
            #pragma unroll
            for (int mt = 0; mt < 4; mt++)
                #pragma unroll
                for (int nt = 0; nt < 4; nt++)
                    mma_f16(acc[mt][nt], af[mt], &bf[nt >> 1][(nt & 1) * 2]);
        }
    }
}

// ============ GEMM 1: g_h = gelu(gather(g_xnh) @ w1h + b1)  (+ w2 convert) ====
__global__ __launch_bounds__(256, 2) void gemm1_kernel(
    const float* __restrict__ b1, const float4* __restrict__ w2)
{
    const int tid = threadIdx.x;

    if (blockIdx.z == NEXP) {
        // w2 fp32->fp16 convert riding in gemm1's grid
        const int n4 = NEXP * HDIM * DDIM / 4;
        uint2* o2 = (uint2*)g_w2h;
        const int nblk = gridDim.x * gridDim.y;
        const int bid = blockIdx.y * gridDim.x + blockIdx.x;
        for (int i = bid * 256 + tid; i < n4; i += nblk * 256) {
            float4 v = w2[i];
            uint2 o;
            o.x = pack_h2(v.x, v.y);
            o.y = pack_h2(v.z, v.w);
            o2[i] = o;
        }
        return;
    }

    const int e = blockIdx.z;
    const int cnt = g_cnt[e];
    const int m0 = blockIdx.y * 128;
    if (m0 >= cnt) return;
    const int n0 = blockIdx.x * 128;

    extern __shared__ char smem[];
    const uint32_t sA = smem_u32(smem);
    const uint32_t sB = sA + NSTAGE * ABUF_H * 2;
    int* s_tok = (int*)(smem + NSTAGE * (ABUF_H + BBUF_H) * 2);

    if (tid < 128)
        s_tok[tid] = (m0 + tid < cnt) ? g_tok[e * NTOK + m0 + tid] : 0;
    __syncthreads();

    const int arow = tid >> 3;
    const int acol = (tid & 7) * 8;
    const __half* ap[4];
    uint32_t ab[4];
    #pragma unroll
    for (int i = 0; i < 4; i++) {
        int m = m0 + arow + 32 * i;
        bool valid = m < cnt;
        ap[i] = g_xnh + (size_t)s_tok[arow + 32 * i] * DDIM + acol;
        ab[i] = valid ? 16u : 0u;
    }
    const int brow = tid >> 4;
    const int bcol = (tid & 15) * 8;
    const __half* bp[4];
    #pragma unroll
    for (int i = 0; i < 4; i++)
        bp[i] = g_w1h + (size_t)e * DDIM * HDIM + (size_t)(brow + 16 * i) * HDIM + n0 + bcol;

    float acc[4][4][4];
    #pragma unroll
    for (int mt = 0; mt < 4; mt++)
        #pragma unroll
        for (int nt = 0; nt < 4; nt++)
            #pragma unroll
            for (int q = 0; q < 4; q++) acc[mt][nt][q] = 0.f;

    gemm_mainloop(sA, sB, ap[0], ap[1], ap[2], ap[3], ab[0], ab[1], ab[2], ab[3],
                  bp[0], bp[1], bp[2], bp[3], (size_t)BKH * HDIM,
                  DDIM / BKH, acc);

    const int lane = tid & 31;
    const int warp = tid >> 5;
    const int wm64 = (warp >> 2) * 64;
    const int wn32 = (warp & 3) * 32;
    const int gr = lane >> 2, tg = lane & 3;

    const float* b1e = b1 + (size_t)e * HDIM + n0;
    #pragma unroll
    for (int mt = 0; mt < 4; mt++) {
        #pragma unroll
        for (int half = 0; half < 2; half++) {
            int m = m0 + wm64 + mt * 16 + gr + 8 * half;
            if (m >= cnt) continue;
            __half* hrow = g_h + ((size_t)e * NTOK + m) * HDIM + n0;
            #pragma unroll
            for (int nt = 0; nt < 4; nt++) {
                int c = wn32 + nt * 8 + 2 * tg;
                float v0 = acc[mt][nt][2 * half + 0] + b1e[c];
                float v1 = acc[mt][nt][2 * half + 1] + b1e[c + 1];
                v0 = 0.5f * v0 * (1.0f + erff(v0 * 0.70710678118654752f));
                v1 = 0.5f * v1 * (1.0f + erff(v1 * 0.70710678118654752f));
                *(uint32_t*)(hrow + c) = pack_h2(v0, v1);
            }
        }
    }
}

// ============ GEMM 2 (split-K=2): out += gate * (g_h @ w2h + b2) ==============
// Last CTA to retire also writes the balance loss (fused finish).
__global__ __launch_bounds__(256, 2) void gemm2_kernel(
    const float* __restrict__ b2, float* __restrict__ out)
{
    const int e = blockIdx.z >> 1;
    const int ksl = blockIdx.z & 1;
    const int cnt = g_cnt[e];
    const int m0 = blockIdx.y * 128;
    const int n0 = blockIdx.x * 128;
    const int tid = threadIdx.x;
    const int total = gridDim.x * gridDim.y * gridDim.z;

    extern __shared__ char smem[];

    if (m0 < cnt) {
        const uint32_t sA = smem_u32(smem);
        const uint32_t sB = sA + NSTAGE * ABUF_H * 2;
        int*   s_tok  = (int*)(smem + NSTAGE * (ABUF_H + BBUF_H) * 2);
        float* s_gate = (float*)(s_tok + 128);

        if (tid < 128) {
            bool v = m0 + tid < cnt;
            s_tok[tid]  = v ? g_tok[e * NTOK + m0 + tid] : 0;
            s_gate[tid] = v ? g_gate[e * NTOK + m0 + tid] : 0.f;
        }
        __syncthreads();

        const int arow = tid >> 3;
        const int acol = (tid & 7) * 8;
        const __half* ap[4];
        uint32_t ab[4];
        #pragma unroll
        for (int i = 0; i < 4; i++) {
            int m = m0 + arow + 32 * i;
            bool valid = m < cnt;
            ap[i] = g_h + ((size_t)e * NTOK + (valid ? m : m0)) * HDIM +
                    ksl * KSLICE + acol;
            ab[i] = valid ? 16u : 0u;
        }
        const int brow = tid >> 4;
        const int bcol = (tid & 15) * 8;
        const __half* bp[4];
        #pragma unroll
        for (int i = 0; i < 4; i++)
            bp[i] = g_w2h + (size_t)e * HDIM * DDIM +
                    (size_t)(ksl * KSLICE + brow + 16 * i) * DDIM + n0 + bcol;

        float acc[4][4][4];
        #pragma unroll
        for (int mt = 0; mt < 4; mt++)
            #pragma unroll
            for (int nt = 0; nt < 4; nt++)
                #pragma unroll
                for (int q = 0; q < 4; q++) acc[mt][nt][q] = 0.f;

        gemm_mainloop(sA, sB, ap[0], ap[1], ap[2], ap[3], ab[0], ab[1], ab[2], ab[3],
                      bp[0], bp[1], bp[2], bp[3], (size_t)BKH * DDIM,
                      KSLICE / BKH, acc);

        const int lane = tid & 31;
        const int warp = tid >> 5;
        const int wm64 = (warp >> 2) * 64;
        const int wn32 = (warp & 3) * 32;
        const int gr = lane >> 2, tg = lane & 3;

        const float* b2e = b2 + (size_t)e * DDIM + n0;
        const float bias_scale = (ksl == 0) ? 1.0f : 0.0f;
        #pragma unroll
        for (int mt = 0; mt < 4; mt++) {
            #pragma unroll
            for (int half = 0; half < 2; half++) {
                int ml = wm64 + mt * 16 + gr + 8 * half;
                if (m0 + ml >= cnt) continue;
                int token = s_tok[ml];
                float gate = s_gate[ml];
                float* orow = out + (size_t)token * DDIM + n0;
                #pragma unroll
                for (int nt = 0; nt < 4; nt++) {
                    int c = wn32 + nt * 8 + 2 * tg;
                    float v0 = acc[mt][nt][2 * half + 0] + bias_scale * b2e[c];
                    float v1 = acc[mt][nt][2 * half + 1] + bias_scale * b2e[c + 1];
                    atomicAdd(&orow[c], gate * v0);
                    atomicAdd(&orow[c + 1], gate * v1);
                }
            }
        }
        __syncthreads();
    }

    // fused finish: last CTA writes balance loss (uses only prep's counters)
    if (tid == 0) {
        int old = atomicAdd(&g_g2done, 1);
        if (old == total - 1) {
            float acc = 0.f;
            #pragma unroll
            for (int q = 0; q < NEXP; q++) acc += (float)g_cnt[q] * g_psum[q];
            out[(size_t)NTOK * DDIM] =
                0.01f * (float)NEXP * acc / ((float)NTOK * (float)NTOK);
        }
    }
}

// ---------------- launch ----------------
extern "C" void kernel_launch(void* const* d_in, const int* in_sizes, int n_in,
                              void* d_out, int out_size)
{
    const float* x     = (const float*)d_in[0];
    const float* gamma = (const float*)d_in[1];
    const float* beta  = (const float*)d_in[2];
    const float* gw    = (const float*)d_in[3];
    const float* w1    = (const float*)d_in[4];
    const float* b1    = (const float*)d_in[5];
    const float* w2    = (const float*)d_in[6];
    const float* b2    = (const float*)d_in[7];
    float* out = (float*)d_out;

    cudaFuncSetAttribute(gemm1_kernel, cudaFuncAttributeMaxDynamicSharedMemorySize, SMEM_BYTES);
    cudaFuncSetAttribute(gemm2_kernel, cudaFuncAttributeMaxDynamicSharedMemorySize, SMEM_BYTES);

    zero_kernel<<<1, 32>>>();
    prep_kernel<<<NTOK + CONVBLKS, 256>>>(x, gamma, beta, gw,
                                          (const float4*)w1,
                                          out, out + (size_t)NTOK * DDIM + 1);

    // z slice NEXP carries the w2 convert blocks
    gemm1_kernel<<<dim3(HDIM / 128, NTOK / 128, NEXP + 1), 256, SMEM_BYTES>>>(
        b1, (const float4*)w2);
    gemm2_kernel<<<dim3(DDIM / 128, NTOK / 128, NEXP * SPLITK), 256, SMEM_BYTES>>>(b2, out);
}

// round 15
// speedup vs baseline: 1.1087x; 1.0041x over previous
#include <cuda_runtime.h>
#include <cuda_fp16.h>
#include <math.h>
#include <stdint.h>

#define NTOK 4096
#define DDIM 1024
#define NEXP 8
#define HDIM 4096
#define BKH 64            // k per tile (halves)
#define CONVBLKS 1024
#define SPLITK 2
#define KSLICE (HDIM / SPLITK)

// ---------------- scratch ----------------
__device__ __half g_xnh[(size_t)NTOK * DDIM];                  // normalized x, fp16
__device__ __half g_w1h[(size_t)NEXP * DDIM * HDIM];           // w1 fp16
__device__ __half g_w2h[(size_t)NEXP * HDIM * DDIM];           // w2 fp16
__device__ __half g_h[(size_t)NEXP * NTOK * HDIM];             // hidden, fp16
__device__ int    g_cnt[NEXP];
__device__ float  g_psum[NEXP];
__device__ int    g_tok[NEXP * NTOK];
__device__ float  g_gate[NEXP * NTOK];
__device__ int    g_g2done;

// ---------------- helpers ----------------
__device__ __forceinline__ uint32_t smem_u32(const void* p) {
    uint32_t a;
    asm("{ .reg .u64 t; cvta.to.shared.u64 t, %1; cvt.u32.u64 %0, t; }" : "=r"(a) : "l"(p));
    return a;
}
__device__ __forceinline__ uint32_t pack_h2(float a, float b) {
    __half2 h = __floats2half2_rn(a, b);
    return *(uint32_t*)&h;
}
// .cg: L2-only path (no L1 fill) — GEMM tiles have no L1 reuse
#define CP16(dst, src) \
    asm volatile("cp.async.cg.shared.global [%0], [%1], 16;" :: "r"(dst), "l"(src))
#define CP16Z(dst, src, bytes) \
    asm volatile("cp.async.cg.shared.global [%0], [%1], 16, %2;" :: "r"(dst), "l"(src), "r"(bytes))
#define CP_COMMIT() asm volatile("cp.async.commit_group;" ::: "memory")
#define CP_WAIT1()  asm volatile("cp.async.wait_group 1;" ::: "memory")

#define LDSM_X4(r0, r1, r2, r3, addr) \
    asm volatile("ldmatrix.sync.aligned.m8n8.x4.shared.b16 {%0,%1,%2,%3}, [%4];" \
        : "=r"(r0), "=r"(r1), "=r"(r2), "=r"(r3) : "r"(addr))
#define LDSM_X4T(r0, r1, r2, r3, addr) \
    asm volatile("ldmatrix.sync.aligned.m8n8.x4.trans.shared.b16 {%0,%1,%2,%3}, [%4];" \
        : "=r"(r0), "=r"(r1), "=r"(r2), "=r"(r3) : "r"(addr))

__device__ __forceinline__ void mma_f16(float* d, const uint32_t* a, const uint32_t* b) {
    asm volatile(
        "mma.sync.aligned.m16n8k16.row.col.f32.f16.f16.f32 "
        "{%0,%1,%2,%3}, {%4,%5,%6,%7}, {%8,%9}, {%0,%1,%2,%3};"
        : "+f"(d[0]), "+f"(d[1]), "+f"(d[2]), "+f"(d[3])
        : "r"(a[0]), "r"(a[1]), "r"(a[2]), "r"(a[3]), "r"(b[0]), "r"(b[1]));
}

// smem strides in halves (stride mod 128B = 16B -> conflict-free ldmatrix)
#define AST 72
#define BST 136
#define ABUF_H (128 * AST)
#define BBUF_H (BKH * BST)
#define NSTAGE 3
#define SMEM_BYTES ((NSTAGE * (ABUF_H + BBUF_H)) * 2 + 1024 + 128)

// ---------------- reset counters ----------------
__global__ void zero_kernel() {
    int t = threadIdx.x;
    if (t < NEXP) { g_cnt[t] = 0; g_psum[t] = 0.0f; }
    if (t == 0) g_g2done = 0;
}

// ---------------- merged prep: w1 convert FIRST (long pole), then LN+router ----
__global__ __launch_bounds__(256) void prep_kernel(
    const float* __restrict__ x, const float* __restrict__ gamma,
    const float* __restrict__ beta, const float* __restrict__ gw,
    const float4* __restrict__ w1,
    float* __restrict__ out, float* __restrict__ probs_out)
{
    const int tid = threadIdx.x;

    if (blockIdx.x < CONVBLKS) {
        // convert blocks dispatch in wave 1 — long pole starts at t=0
        const int n4 = NEXP * DDIM * HDIM / 4;
        uint2* o1 = (uint2*)g_w1h;
        for (int i = blockIdx.x * 256 + tid; i < n4; i += CONVBLKS * 256) {
            float4 v = w1[i];
            uint2 o;
            o.x = pack_h2(v.x, v.y);
            o.y = pack_h2(v.z, v.w);
            o1[i] = o;
        }
        return;
    }

    const int n = blockIdx.x - CONVBLKS;
    const int lane = tid & 31, warp = tid >> 5;

    float4 v = reinterpret_cast<const float4*>(x + (size_t)n * DDIM)[tid];
    // residual base: out = x
    reinterpret_cast<float4*>(out + (size_t)n * DDIM)[tid] = v;

    float s  = v.x + v.y + v.z + v.w;
    float ss = v.x * v.x + v.y * v.y + v.z * v.z + v.w * v.w;

    __shared__ float rs[8], rss[8];
    #pragma unroll
    for (int o = 16; o; o >>= 1) {
        s  += __shfl_down_sync(0xffffffffu, s, o);
        ss += __shfl_down_sync(0xffffffffu, ss, o);
    }
    if (lane == 0) { rs[warp] = s; rss[warp] = ss; }
    __syncthreads();

    __shared__ float s_mu, s_rstd;
    if (tid == 0) {
        float S = 0.f, SS = 0.f;
        #pragma unroll
        for (int i = 0; i < 8; i++) { S += rs[i]; SS += rss[i]; }
        float mu = S / (float)DDIM;
        float var = SS / (float)DDIM - mu * mu;
        s_mu = mu; s_rstd = rsqrtf(var + 1e-5f);
    }
    __syncthreads();
    const float mu = s_mu, r = s_rstd;

    float4 g4 = reinterpret_cast<const float4*>(gamma)[tid];
    float4 b4 = reinterpret_cast<const float4*>(beta)[tid];
    float xn0 = (v.x - mu) * r * g4.x + b4.x;
    float xn1 = (v.y - mu) * r * g4.y + b4.y;
    float xn2 = (v.z - mu) * r * g4.z + b4.z;
    float xn3 = (v.w - mu) * r * g4.w + b4.w;
    {
        uint2 o;
        o.x = pack_h2(xn0, xn1);
        o.y = pack_h2(xn2, xn3);
        reinterpret_cast<uint2*>(g_xnh + (size_t)n * DDIM)[tid] = o;
    }

    float lg[NEXP];
    {
        const float4* gwr = reinterpret_cast<const float4*>(gw + (size_t)tid * 4 * NEXP);
        float4 a0 = gwr[0], a1 = gwr[1];
        float4 c0 = gwr[2], c1 = gwr[3];
        float4 d0 = gwr[4], d1 = gwr[5];
        float4 e0 = gwr[6], e1 = gwr[7];
        lg[0] = xn0*a0.x + xn1*c0.x + xn2*d0.x + xn3*e0.x;
        lg[1] = xn0*a0.y + xn1*c0.y + xn2*d0.y + xn3*e0.y;
        lg[2] = xn0*a0.z + xn1*c0.z + xn2*d0.z + xn3*e0.z;
        lg[3] = xn0*a0.w + xn1*c0.w + xn2*d0.w + xn3*e0.w;
        lg[4] = xn0*a1.x + xn1*c1.x + xn2*d1.x + xn3*e1.x;
        lg[5] = xn0*a1.y + xn1*c1.y + xn2*d1.y + xn3*e1.y;
        lg[6] = xn0*a1.z + xn1*c1.z + xn2*d1.z + xn3*e1.z;
        lg[7] = xn0*a1.w + xn1*c1.w + xn2*d1.w + xn3*e1.w;
    }

    __shared__ float sl[8][NEXP];
    #pragma unroll
    for (int e = 0; e < NEXP; e++) {
        float t = lg[e];
        #pragma unroll
        for (int o = 16; o; o >>= 1) t += __shfl_down_sync(0xffffffffu, t, o);
        if (lane == 0) sl[warp][e] = t;
    }
    __syncthreads();

    if (tid == 0) {
        float logit[NEXP];
        #pragma unroll
        for (int e = 0; e < NEXP; e++) {
            float t = 0.f;
            #pragma unroll
            for (int w = 0; w < 8; w++) t += sl[w][e];
            logit[e] = t;
        }
        float mx = logit[0];
        #pragma unroll
        for (int e = 1; e < NEXP; e++) mx = fmaxf(mx, logit[e]);
        float p[NEXP], denom = 0.f;
        #pragma unroll
        for (int e = 0; e < NEXP; e++) { p[e] = expf(logit[e] - mx); denom += p[e]; }
        float inv = 1.0f / denom;
        #pragma unroll
        for (int e = 0; e < NEXP; e++) {
            p[e] *= inv;
            probs_out[(size_t)n * NEXP + e] = p[e];
            atomicAdd(&g_psum[e], p[e]);
        }
        int i1 = 0;
        #pragma unroll
        for (int e = 1; e < NEXP; e++) if (p[e] > p[i1]) i1 = e;
        int i2 = (i1 == 0) ? 1 : 0;
        #pragma unroll
        for (int e = 0; e < NEXP; e++) if (e != i1 && p[e] > p[i2]) i2 = e;
        float wsum = p[i1] + p[i2] + 1e-8f;
        float w1v = p[i1] / wsum, w2v = p[i2] / wsum;
        int r1 = atomicAdd(&g_cnt[i1], 1);
        g_tok[i1 * NTOK + r1] = n; g_gate[i1 * NTOK + r1] = w1v;
        int r2 = atomicAdd(&g_cnt[i2], 1);
        g_tok[i2 * NTOK + r2] = n; g_gate[i2 * NTOK + r2] = w2v;
    }
}

// ============ fp16 HMMA GEMM core: BM=128,BN=128,BK=64, 256 threads ============
// 8 warps (2x4), warp tile 64x32, 3-stage cp.async ring, ldmatrix fragments.

__device__ __forceinline__ void gemm_mainloop(
    uint32_t sA, uint32_t sB,
    const __half* aptr0, const __half* aptr1, const __half* aptr2, const __half* aptr3,
    uint32_t ab0, uint32_t ab1, uint32_t ab2, uint32_t ab3,
    const __half* bptr0, const __half* bptr1, const __half* bptr2, const __half* bptr3,
    size_t b_adv,
    int NK, float acc[4][4][4])
{
    const int tid = threadIdx.x;
    const int lane = tid & 31;
    const int warp = tid >> 5;
    const int wm64 = (warp >> 2) * 64;
    const int wn32 = (warp & 3) * 32;

    const uint32_t a_soff = (uint32_t)(((tid >> 3) * AST + (tid & 7) * 8) * 2);
    const uint32_t b_soff = (uint32_t)(((tid >> 4) * BST + (tid & 15) * 8) * 2);
    const uint32_t a_rstep = (uint32_t)(32 * AST * 2);
    const uint32_t b_rstep = (uint32_t)(16 * BST * 2);

    const int lrow = (lane & 7) + 8 * ((lane >> 3) & 1);
    const int lhi  = 8 * (lane >> 4);
    uint32_t aoff[4], boff[2];
    #pragma unroll
    for (int mt = 0; mt < 4; mt++)
        aoff[mt] = (uint32_t)(((wm64 + mt * 16 + lrow) * AST + lhi) * 2);
    #pragma unroll
    for (int np = 0; np < 2; np++)
        boff[np] = (uint32_t)((lrow * BST + wn32 + np * 16 + lhi) * 2);

    const __half* ap[4] = {aptr0, aptr1, aptr2, aptr3};
    uint32_t ab[4] = {ab0, ab1, ab2, ab3};
    const __half* bp[4] = {bptr0, bptr1, bptr2, bptr3};

    // prologue: tiles 0 and 1
    #pragma unroll
    for (int st = 0; st < 2; st++) {
        uint32_t dA = sA + st * (ABUF_H * 2) + a_soff;
        uint32_t dB = sB + st * (BBUF_H * 2) + b_soff;
        #pragma unroll
        for (int i = 0; i < 4; i++) {
            CP16Z(dA + i * a_rstep, ap[i], ab[i]); ap[i] += BKH;
        }
        #pragma unroll
        for (int i = 0; i < 4; i++) {
            CP16(dB + i * b_rstep, bp[i]); bp[i] += b_adv;
        }
        CP_COMMIT();
    }

    for (int ic = 0; ic < NK; ic++) {
        CP_WAIT1();
        __syncthreads();

        if (ic + 2 < NK) {
            const int st = (ic + 2) % NSTAGE;
            uint32_t dA = sA + st * (ABUF_H * 2) + a_soff;
            uint32_t dB = sB + st * (BBUF_H * 2) + b_soff;
            #pragma unroll
            for (int i = 0; i < 4; i++) {
                CP16Z(dA + i * a_rstep, ap[i], ab[i]); ap[i] += BKH;
            }
            #pragma unroll
            for (int i = 0; i < 4; i++) {
                CP16(dB + i * b_rstep, bp[i]); bp[i] += b_adv;
            }
        }
        CP_COMMIT();

        const uint32_t sAt = sA + (ic % NSTAGE) * (ABUF_H * 2);
        const uint32_t sBt = sB + (ic % NSTAGE) * (BBUF_H * 2);
        #pragma unroll
        for (int ks = 0; ks < 4; ks++) {
            uint32_t af[4][4], bf[2][4];
            #pragma unroll
            for (int mt = 0; mt < 4; mt++)
                LDSM_X4(af[mt][0], af[mt][1], af[mt][2], af[mt][3],
                        sAt + aoff[mt] + ks * 32);
            #pragma unroll
            for (int np = 0; np < 2; np++)
                LDSM_X4T(bf[np][0], bf[np][1], bf[np][2], bf[np][3],
                         sBt + boff[np] + ks * 16 * BST * 2);
            #pragma unroll
            for (int mt = 0; mt < 4; mt++)
                #pragma unroll
                for (int nt = 0; nt < 4; nt++)
                    mma_f16(acc[mt][nt], af[mt], &bf[nt >> 1][(nt & 1) * 2]);
        }
    }
}

// ============ GEMM 1: g_h = gelu(gather(g_xnh) @ w1h + b1)  (+ w2 convert) ====
__global__ __launch_bounds__(256, 2) void gemm1_kernel(
    const float* __restrict__ b1, const float4* __restrict__ w2)
{
    const int tid = threadIdx.x;

    if (blockIdx.z == NEXP) {
        // w2 fp32->fp16 convert riding in gemm1's grid
        const int n4 = NEXP * HDIM * DDIM / 4;
        uint2* o2 = (uint2*)g_w2h;
        const int nblk = gridDim.x * gridDim.y;
        const int bid = blockIdx.y * gridDim.x + blockIdx.x;
        for (int i = bid * 256 + tid; i < n4; i += nblk * 256) {
            float4 v = w2[i];
            uint2 o;
            o.x = pack_h2(v.x, v.y);
            o.y = pack_h2(v.z, v.w);
            o2[i] = o;
        }
        return;
    }

    const int e = blockIdx.z;
    const int cnt = g_cnt[e];
    const int m0 = blockIdx.y * 128;
    if (m0 >= cnt) return;
    const int n0 = blockIdx.x * 128;

    extern __shared__ char smem[];
    const uint32_t sA = smem_u32(smem);
    const uint32_t sB = sA + NSTAGE * ABUF_H * 2;
    int* s_tok = (int*)(smem + NSTAGE * (ABUF_H + BBUF_H) * 2);

    if (tid < 128)
        s_tok[tid] = (m0 + tid < cnt) ? g_tok[e * NTOK + m0 + tid] : 0;
    __syncthreads();

    const int arow = tid >> 3;
    const int acol = (tid & 7) * 8;
    const __half* ap[4];
    uint32_t ab[4];
    #pragma unroll
    for (int i = 0; i < 4; i++) {
        int m = m0 + arow + 32 * i;
        bool valid = m < cnt;
        ap[i] = g_xnh + (size_t)s_tok[arow + 32 * i] * DDIM + acol;
        ab[i] = valid ? 16u : 0u;
    }
    const int brow = tid >> 4;
    const int bcol = (tid & 15) * 8;
    const __half* bp[4];
    #pragma unroll
    for (int i = 0; i < 4; i++)
        bp[i] = g_w1h + (size_t)e * DDIM * HDIM + (size_t)(brow + 16 * i) * HDIM + n0 + bcol;

    float acc[4][4][4];
    #pragma unroll
    for (int mt = 0; mt < 4; mt++)
        #pragma unroll
        for (int nt = 0; nt < 4; nt++)
            #pragma unroll
            for (int q = 0; q < 4; q++) acc[mt][nt][q] = 0.f;

    gemm_mainloop(sA, sB, ap[0], ap[1], ap[2], ap[3], ab[0], ab[1], ab[2], ab[3],
                  bp[0], bp[1], bp[2], bp[3], (size_t)BKH * HDIM,
                  DDIM / BKH, acc);

    const int lane = tid & 31;
    const int warp = tid >> 5;
    const int wm64 = (warp >> 2) * 64;
    const int wn32 = (warp & 3) * 32;
    const int gr = lane >> 2, tg = lane & 3;

    const float* b1e = b1 + (size_t)e * HDIM + n0;
    #pragma unroll
    for (int mt = 0; mt < 4; mt++) {
        #pragma unroll
        for (int half = 0; half < 2; half++) {
            int m = m0 + wm64 + mt * 16 + gr + 8 * half;
            if (m >= cnt) continue;
            __half* hrow = g_h + ((size_t)e * NTOK + m) * HDIM + n0;
            #pragma unroll
            for (int nt = 0; nt < 4; nt++) {
                int c = wn32 + nt * 8 + 2 * tg;
                float v0 = acc[mt][nt][2 * half + 0] + b1e[c];
                float v1 = acc[mt][nt][2 * half + 1] + b1e[c + 1];
                v0 = 0.5f * v0 * (1.0f + erff(v0 * 0.70710678118654752f));
                v1 = 0.5f * v1 * (1.0f + erff(v1 * 0.70710678118654752f));
                *(uint32_t*)(hrow + c) = pack_h2(v0, v1);
            }
        }
    }
}

// ============ GEMM 2 (split-K=2): out += gate * (g_h @ w2h + b2) ==============
// Last CTA to retire also writes the balance loss (fused finish).
__global__ __launch_bounds__(256, 2) void gemm2_kernel(
    const float* __restrict__ b2, float* __restrict__ out)
{
    const int e = blockIdx.z >> 1;
    const int ksl = blockIdx.z & 1;
    const int cnt = g_cnt[e];
    const int m0 = blockIdx.y * 128;
    const int n0 = blockIdx.x * 128;
    const int tid = threadIdx.x;
    const int total = gridDim.x * gridDim.y * gridDim.z;

    extern __shared__ char smem[];

    if (m0 < cnt) {
        const uint32_t sA = smem_u32(smem);
        const uint32_t sB = sA + NSTAGE * ABUF_H * 2;

        const int arow = tid >> 3;
        const int acol = (tid & 7) * 8;
        const __half* ap[4];
        uint32_t ab[4];
        #pragma unroll
        for (int i = 0; i < 4; i++) {
            int m = m0 + arow + 32 * i;
            bool valid = m < cnt;
            ap[i] = g_h + ((size_t)e * NTOK + (valid ? m : m0)) * HDIM +
                    ksl * KSLICE + acol;
            ab[i] = valid ? 16u : 0u;
        }
        const int brow = tid >> 4;
        const int bcol = (tid & 15) * 8;
        const __half* bp[4];
        #pragma unroll
        for (int i = 0; i < 4; i++)
            bp[i] = g_w2h + (size_t)e * HDIM * DDIM +
                    (size_t)(ksl * KSLICE + brow + 16 * i) * DDIM + n0 + bcol;

        float acc[4][4][4];
        #pragma unroll
        for (int mt = 0; mt < 4; mt++)
            #pragma unroll
            for (int nt = 0; nt < 4; nt++)
                #pragma unroll
                for (int q = 0; q < 4; q++) acc[mt][nt][q] = 0.f;

        gemm_mainloop(sA, sB, ap[0], ap[1], ap[2], ap[3], ab[0], ab[1], ab[2], ab[3],
                      bp[0], bp[1], bp[2], bp[3], (size_t)BKH * DDIM,
                      KSLICE / BKH, acc);

        const int lane = tid & 31;
        const int warp = tid >> 5;
        const int wm64 = (warp >> 2) * 64;
        const int wn32 = (warp & 3) * 32;
        const int gr = lane >> 2, tg = lane & 3;

        const float* b2e = b2 + (size_t)e * DDIM + n0;
        const float bias_scale = (ksl == 0) ? 1.0f : 0.0f;
        #pragma unroll
        for (int mt = 0; mt < 4; mt++) {
            #pragma unroll
            for (int half = 0; half < 2; half++) {
                int m = m0 + wm64 + mt * 16 + gr + 8 * half;
                if (m >= cnt) continue;
                int token = g_tok[e * NTOK + m];
                float gate = g_gate[e * NTOK + m];
                float* orow = out + (size_t)token * DDIM + n0;
                #pragma unroll
                for (int nt = 0; nt < 4; nt++) {
                    int c = wn32 + nt * 8 + 2 * tg;
                    float v0 = acc[mt][nt][2 * half + 0] + bias_scale * b2e[c];
                    float v1 = acc[mt][nt][2 * half + 1] + bias_scale * b2e[c + 1];
                    atomicAdd(&orow[c], gate * v0);
                    atomicAdd(&orow[c + 1], gate * v1);
                }
            }
        }
    }

    // fused finish: last CTA writes balance loss (uses only prep's counters)
    if (tid == 0) {
        int old = atomicAdd(&g_g2done, 1);
        if (old == total - 1) {
            float acc = 0.f;
            #pragma unroll
            for (int q = 0; q < NEXP; q++) acc += (float)g_cnt[q] * g_psum[q];
            out[(size_t)NTOK * DDIM] =
                0.01f * (float)NEXP * acc / ((float)NTOK * (float)NTOK);
        }
    }
}

// ---------------- launch ----------------
extern "C" void kernel_launch(void* const* d_in, const int* in_sizes, int n_in,
                              void* d_out, int out_size)
{
    const float* x     = (const float*)d_in[0];
    const float* gamma = (const float*)d_in[1];
    const float* beta  = (const float*)d_in[2];
    const float* gw    = (const float*)d_in[3];
    const float* w1    = (const float*)d_in[4];
    const float* b1    = (const float*)d_in[5];
    const float* w2    = (const float*)d_in[6];
    const float* b2    = (const float*)d_in[7];
    float* out = (float*)d_out;

    cudaFuncSetAttribute(gemm1_kernel, cudaFuncAttributeMaxDynamicSharedMemorySize, SMEM_BYTES);
    cudaFuncSetAttribute(gemm2_kernel, cudaFuncAttributeMaxDynamicSharedMemorySize, SMEM_BYTES);

    zero_kernel<<<1, 32>>>();
    prep_kernel<<<NTOK + CONVBLKS, 256>>>(x, gamma, beta, gw,
                                          (const float4*)w1,
                                          out, out + (size_t)NTOK * DDIM + 1);

    // z slice NEXP carries the w2 convert blocks
    gemm1_kernel<<<dim3(HDIM / 128, NTOK / 128, NEXP + 1), 256, SMEM_BYTES>>>(
        b1, (const float4*)w2);
    gemm2_kernel<<<dim3(DDIM / 128, NTOK / 128, NEXP * SPLITK), 256, SMEM_BYTES>>>(b2, out);
}

// round 16
// speedup vs baseline: 1.1276x; 1.0170x over previous
#include <cuda_runtime.h>
#include <cuda_fp16.h>
#include <math.h>
#include <stdint.h>

#define NTOK 4096
#define DDIM 1024
#define NEXP 8
#define HDIM 4096
#define BKH 64            // k per tile (halves)
#define CONVBLKS 1024
#define SPLITK 2
#define KSLICE (HDIM / SPLITK)

// ---------------- scratch (zero-initialized at module load) ----------------
__device__ __half g_xnh[(size_t)NTOK * DDIM];
__device__ __half g_w1h[(size_t)NEXP * DDIM * HDIM];
__device__ __half g_w2h[(size_t)NEXP * HDIM * DDIM];
__device__ __half g_h[(size_t)NEXP * NTOK * HDIM];
__device__ int    g_cnt[NEXP];
__device__ float  g_psum[NEXP];
__device__ int    g_tok[NEXP * NTOK];
__device__ float  g_gate[NEXP * NTOK];
__device__ int    g_g2done;

// ---------------- helpers ----------------
__device__ __forceinline__ uint32_t smem_u32(const void* p) {
    uint32_t a;
    asm("{ .reg .u64 t; cvta.to.shared.u64 t, %1; cvt.u32.u64 %0, t; }" : "=r"(a) : "l"(p));
    return a;
}
__device__ __forceinline__ uint32_t pack_h2(float a, float b) {
    __half2 h = __floats2half2_rn(a, b);
    return *(uint32_t*)&h;
}
// fast GELU (tanh form via sigmoid): max abs dev from exact ~3e-4
__device__ __forceinline__ float gelu_fast(float x) {
    float u = 1.5957691216f * fmaf(0.044715f * x, x * x, x);
    return __fdividef(x, 1.0f + __expf(-u));
}
// .cg: L2-only path (no L1 fill) — GEMM tiles have no L1 reuse
#define CP16(dst, src) \
    asm volatile("cp.async.cg.shared.global [%0], [%1], 16;" :: "r"(dst), "l"(src))
#define CP16Z(dst, src, bytes) \
    asm volatile("cp.async.cg.shared.global [%0], [%1], 16, %2;" :: "r"(dst), "l"(src), "r"(bytes))
#define CP_COMMIT() asm volatile("cp.async.commit_group;" ::: "memory")
#define CP_WAIT1()  asm volatile("cp.async.wait_group 1;" ::: "memory")

#define LDSM_X4(r0, r1, r2, r3, addr) \
    asm volatile("ldmatrix.sync.aligned.m8n8.x4.shared.b16 {%0,%1,%2,%3}, [%4];" \
        : "=r"(r0), "=r"(r1), "=r"(r2), "=r"(r3) : "r"(addr))
#define LDSM_X4T(r0, r1, r2, r3, addr) \
    asm volatile("ldmatrix.sync.aligned.m8n8.x4.trans.shared.b16 {%0,%1,%2,%3}, [%4];" \
        : "=r"(r0), "=r"(r1), "=r"(r2), "=r"(r3) : "r"(addr))

__device__ __forceinline__ void mma_f16(float* d, const uint32_t* a, const uint32_t* b) {
    asm volatile(
        "mma.sync.aligned.m16n8k16.row.col.f32.f16.f16.f32 "
        "{%0,%1,%2,%3}, {%4,%5,%6,%7}, {%8,%9}, {%0,%1,%2,%3};"
        : "+f"(d[0]), "+f"(d[1]), "+f"(d[2]), "+f"(d[3])
        : "r"(a[0]), "r"(a[1]), "r"(a[2]), "r"(a[3]), "r"(b[0]), "r"(b[1]));
}

// smem strides in halves (stride mod 128B = 16B -> conflict-free ldmatrix)
#define AST 72
#define BST 136
#define ABUF_H (128 * AST)
#define BBUF_H (BKH * BST)
#define NSTAGE 3
#define SMEM_BYTES ((NSTAGE * (ABUF_H + BBUF_H)) * 2 + 1024 + 128)

// ---------------- merged prep: w1 convert FIRST (long pole), then LN+router ----
__global__ __launch_bounds__(256) void prep_kernel(
    const float* __restrict__ x, const float* __restrict__ gamma,
    const float* __restrict__ beta, const float* __restrict__ gw,
    const float4* __restrict__ w1,
    float* __restrict__ out, float* __restrict__ probs_out)
{
    const int tid = threadIdx.x;

    if (blockIdx.x < CONVBLKS) {
        const int n4 = NEXP * DDIM * HDIM / 4;
        uint2* o1 = (uint2*)g_w1h;
        for (int i = blockIdx.x * 256 + tid; i < n4; i += CONVBLKS * 256) {
            float4 v = w1[i];
            uint2 o;
            o.x = pack_h2(v.x, v.y);
            o.y = pack_h2(v.z, v.w);
            o1[i] = o;
        }
        return;
    }

    const int n = blockIdx.x - CONVBLKS;
    const int lane = tid & 31, warp = tid >> 5;

    float4 v = reinterpret_cast<const float4*>(x + (size_t)n * DDIM)[tid];
    // residual base: out = x
    reinterpret_cast<float4*>(out + (size_t)n * DDIM)[tid] = v;

    float s  = v.x + v.y + v.z + v.w;
    float ss = v.x * v.x + v.y * v.y + v.z * v.z + v.w * v.w;

    __shared__ float rs[8], rss[8];
    #pragma unroll
    for (int o = 16; o; o >>= 1) {
        s  += __shfl_down_sync(0xffffffffu, s, o);
        ss += __shfl_down_sync(0xffffffffu, ss, o);
    }
    if (lane == 0) { rs[warp] = s; rss[warp] = ss; }
    __syncthreads();

    __shared__ float s_mu, s_rstd;
    if (tid == 0) {
        float S = 0.f, SS = 0.f;
        #pragma unroll
        for (int i = 0; i < 8; i++) { S += rs[i]; SS += rss[i]; }
        float mu = S / (float)DDIM;
        float var = SS / (float)DDIM - mu * mu;
        s_mu = mu; s_rstd = rsqrtf(var + 1e-5f);
    }
    __syncthreads();
    const float mu = s_mu, r = s_rstd;

    float4 g4 = reinterpret_cast<const float4*>(gamma)[tid];
    float4 b4 = reinterpret_cast<const float4*>(beta)[tid];
    float xn0 = (v.x - mu) * r * g4.x + b4.x;
    float xn1 = (v.y - mu) * r * g4.y + b4.y;
    float xn2 = (v.z - mu) * r * g4.z + b4.z;
    float xn3 = (v.w - mu) * r * g4.w + b4.w;
    {
        uint2 o;
        o.x = pack_h2(xn0, xn1);
        o.y = pack_h2(xn2, xn3);
        reinterpret_cast<uint2*>(g_xnh + (size_t)n * DDIM)[tid] = o;
    }

    float lg[NEXP];
    {
        const float4* gwr = reinterpret_cast<const float4*>(gw + (size_t)tid * 4 * NEXP);
        float4 a0 = gwr[0], a1 = gwr[1];
        float4 c0 = gwr[2], c1 = gwr[3];
        float4 d0 = gwr[4], d1 = gwr[5];
        float4 e0 = gwr[6], e1 = gwr[7];
        lg[0] = xn0*a0.x + xn1*c0.x + xn2*d0.x + xn3*e0.x;
        lg[1] = xn0*a0.y + xn1*c0.y + xn2*d0.y + xn3*e0.y;
        lg[2] = xn0*a0.z + xn1*c0.z + xn2*d0.z + xn3*e0.z;
        lg[3] = xn0*a0.w + xn1*c0.w + xn2*d0.w + xn3*e0.w;
        lg[4] = xn0*a1.x + xn1*c1.x + xn2*d1.x + xn3*e1.x;
        lg[5] = xn0*a1.y + xn1*c1.y + xn2*d1.y + xn3*e1.y;
        lg[6] = xn0*a1.z + xn1*c1.z + xn2*d1.z + xn3*e1.z;
        lg[7] = xn0*a1.w + xn1*c1.w + xn2*d1.w + xn3*e1.w;
    }

    __shared__ float sl[8][NEXP];
    #pragma unroll
    for (int e = 0; e < NEXP; e++) {
        float t = lg[e];
        #pragma unroll
        for (int o = 16; o; o >>= 1) t += __shfl_down_sync(0xffffffffu, t, o);
        if (lane == 0) sl[warp][e] = t;
    }
    __syncthreads();

    if (tid == 0) {
        float logit[NEXP];
        #pragma unroll
        for (int e = 0; e < NEXP; e++) {
            float t = 0.f;
            #pragma unroll
            for (int w = 0; w < 8; w++) t += sl[w][e];
            logit[e] = t;
        }
        float mx = logit[0];
        #pragma unroll
        for (int e = 1; e < NEXP; e++) mx = fmaxf(mx, logit[e]);
        float p[NEXP], denom = 0.f;
        #pragma unroll
        for (int e = 0; e < NEXP; e++) { p[e] = expf(logit[e] - mx); denom += p[e]; }
        float inv = 1.0f / denom;
        #pragma unroll
        for (int e = 0; e < NEXP; e++) {
            p[e] *= inv;
            probs_out[(size_t)n * NEXP + e] = p[e];
            atomicAdd(&g_psum[e], p[e]);
        }
        int i1 = 0;
        #pragma unroll
        for (int e = 1; e < NEXP; e++) if (p[e] > p[i1]) i1 = e;
        int i2 = (i1 == 0) ? 1 : 0;
        #pragma unroll
        for (int e = 0; e < NEXP; e++) if (e != i1 && p[e] > p[i2]) i2 = e;
        float wsum = p[i1] + p[i2] + 1e-8f;
        float w1v = p[i1] / wsum, w2v = p[i2] / wsum;
        int r1 = atomicAdd(&g_cnt[i1], 1);
        g_tok[i1 * NTOK + r1] = n; g_gate[i1 * NTOK + r1] = w1v;
        int r2 = atomicAdd(&g_cnt[i2], 1);
        g_tok[i2 * NTOK + r2] = n; g_gate[i2 * NTOK + r2] = w2v;
    }
}

// ============ fp16 HMMA GEMM core: BM=128,BN=128,BK=64, 256 threads ============
__device__ __forceinline__ void gemm_mainloop(
    uint32_t sA, uint32_t sB,
    const __half* aptr0, const __half* aptr1, const __half* aptr2, const __half* aptr3,
    uint32_t ab0, uint32_t ab1, uint32_t ab2, uint32_t ab3,
    const __half* bptr0, const __half* bptr1, const __half* bptr2, const __half* bptr3,
    size_t b_adv,
    int NK, float acc[4][4][4])
{
    const int tid = threadIdx.x;
    const int lane = tid & 31;
    const int warp = tid >> 5;
    const int wm64 = (warp >> 2) * 64;
    const int wn32 = (warp & 3) * 32;

    const uint32_t a_soff = (uint32_t)(((tid >> 3) * AST + (tid & 7) * 8) * 2);
    const uint32_t b_soff = (uint32_t)(((tid >> 4) * BST + (tid & 15) * 8) * 2);
    const uint32_t a_rstep = (uint32_t)(32 * AST * 2);
    const uint32_t b_rstep = (uint32_t)(16 * BST * 2);

    const int lrow = (lane & 7) + 8 * ((lane >> 3) & 1);
    const int lhi  = 8 * (lane >> 4);
    uint32_t aoff[4], boff[2];
    #pragma unroll
    for (int mt = 0; mt < 4; mt++)
        aoff[mt] = (uint32_t)(((wm64 + mt * 16 + lrow) * AST + lhi) * 2);
    #pragma unroll
    for (int np = 0; np < 2; np++)
        boff[np] = (uint32_t)((lrow * BST + wn32 + np * 16 + lhi) * 2);

    const __half* ap[4] = {aptr0, aptr1, aptr2, aptr3};
    uint32_t ab[4] = {ab0, ab1, ab2, ab3};
    const __half* bp[4] = {bptr0, bptr1, bptr2, bptr3};

    #pragma unroll
    for (int st = 0; st < 2; st++) {
        uint32_t dA = sA + st * (ABUF_H * 2) + a_soff;
        uint32_t dB = sB + st * (BBUF_H * 2) + b_soff;
        #pragma unroll
        for (int i = 0; i < 4; i++) {
            CP16Z(dA + i * a_rstep, ap[i], ab[i]); ap[i] += BKH;
        }
        #pragma unroll
        for (int i = 0; i < 4; i++) {
            CP16(dB + i * b_rstep, bp[i]); bp[i] += b_adv;
        }
        CP_COMMIT();
    }

    for (int ic = 0; ic < NK; ic++) {
        CP_WAIT1();
        __syncthreads();

        if (ic + 2 < NK) {
            const int st = (ic + 2) % NSTAGE;
            uint32_t dA = sA + st * (ABUF_H * 2) + a_soff;
            uint32_t dB = sB + st * (BBUF_H * 2) + b_soff;
            #pragma unroll
            for (int i = 0; i < 4; i++) {
                CP16Z(dA + i * a_rstep, ap[i], ab[i]); ap[i] += BKH;
            }
            #pragma unroll
            for (int i = 0; i < 4; i++) {
                CP16(dB + i * b_rstep, bp[i]); bp[i] += b_adv;
            }
        }
        CP_COMMIT();

        const uint32_t sAt = sA + (ic % NSTAGE) * (ABUF_H * 2);
        const uint32_t sBt = sB + (ic % NSTAGE) * (BBUF_H * 2);
        #pragma unroll
        for (int ks = 0; ks < 4; ks++) {
            uint32_t af[4][4], bf[2][4];
            #pragma unroll
            for (int mt = 0; mt < 4; mt++)
                LDSM_X4(af[mt][0], af[mt][1], af[mt][2], af[mt][3],
                        sAt + aoff[mt] + ks * 32);
            #pragma unroll
            for (int np = 0; np < 2; np++)
                LDSM_X4T(bf[np][0], bf[np][1], bf[np][2], bf[np][3],
                         sBt + boff[np] + ks * 16 * BST * 2);
            #pragma unroll
            for (int mt = 0; mt < 4; mt++)
                #pragma unroll
                for (int nt = 0; nt < 4; nt++)
                    mma_f16(acc[mt][nt], af[mt], &bf[nt >> 1][(nt & 1) * 2]);
        }
    }
}

// ============ GEMM 1: g_h = gelu(gather(g_xnh) @ w1h + b1)  (+ w2 convert) ====
__global__ __launch_bounds__(256, 2) void gemm1_kernel(
    const float* __restrict__ b1, const float4* __restrict__ w2)
{
    const int tid = threadIdx.x;

    if (blockIdx.z == NEXP) {
        const int n4 = NEXP * HDIM * DDIM / 4;
        uint2* o2 = (uint2*)g_w2h;
        const int nblk = gridDim.x * gridDim.y;
        const int bid = blockIdx.y * gridDim.x + blockIdx.x;
        for (int i = bid * 256 + tid; i < n4; i += nblk * 256) {
            float4 v = w2[i];
            uint2 o;
            o.x = pack_h2(v.x, v.y);
            o.y = pack_h2(v.z, v.w);
            o2[i] = o;
        }
        return;
    }

    const int e = blockIdx.z;
    const int cnt = g_cnt[e];
    const int m0 = blockIdx.y * 128;
    if (m0 >= cnt) return;
    const int n0 = blockIdx.x * 128;

    extern __shared__ char smem[];
    const uint32_t sA = smem_u32(smem);
    const uint32_t sB = sA + NSTAGE * ABUF_H * 2;
    int* s_tok = (int*)(smem + NSTAGE * (ABUF_H + BBUF_H) * 2);

    if (tid < 128)
        s_tok[tid] = (m0 + tid < cnt) ? g_tok[e * NTOK + m0 + tid] : 0;
    __syncthreads();

    const int arow = tid >> 3;
    const int acol = (tid & 7) * 8;
    const __half* ap[4];
    uint32_t ab[4];
    #pragma unroll
    for (int i = 0; i < 4; i++) {
        int m = m0 + arow + 32 * i;
        bool valid = m < cnt;
        ap[i] = g_xnh + (size_t)s_tok[arow + 32 * i] * DDIM + acol;
        ab[i] = valid ? 16u : 0u;
    }
    const int brow = tid >> 4;
    const int bcol = (tid & 15) * 8;
    const __half* bp[4];
    #pragma unroll
    for (int i = 0; i < 4; i++)
        bp[i] = g_w1h + (size_t)e * DDIM * HDIM + (size_t)(brow + 16 * i) * HDIM + n0 + bcol;

    float acc[4][4][4];
    #pragma unroll
    for (int mt = 0; mt < 4; mt++)
        #pragma unroll
        for (int nt = 0; nt < 4; nt++)
            #pragma unroll
            for (int q = 0; q < 4; q++) acc[mt][nt][q] = 0.f;

    gemm_mainloop(sA, sB, ap[0], ap[1], ap[2], ap[3], ab[0], ab[1], ab[2], ab[3],
                  bp[0], bp[1], bp[2], bp[3], (size_t)BKH * HDIM,
                  DDIM / BKH, acc);

    const int lane = tid & 31;
    const int warp = tid >> 5;
    const int wm64 = (warp >> 2) * 64;
    const int wn32 = (warp & 3) * 32;
    const int gr = lane >> 2, tg = lane & 3;

    const float* b1e = b1 + (size_t)e * HDIM + n0;
    #pragma unroll
    for (int mt = 0; mt < 4; mt++) {
        #pragma unroll
        for (int half = 0; half < 2; half++) {
            int m = m0 + wm64 + mt * 16 + gr + 8 * half;
            if (m >= cnt) continue;
            __half* hrow = g_h + ((size_t)e * NTOK + m) * HDIM + n0;
            #pragma unroll
            for (int nt = 0; nt < 4; nt++) {
                int c = wn32 + nt * 8 + 2 * tg;
                float v0 = gelu_fast(acc[mt][nt][2 * half + 0] + b1e[c]);
                float v1 = gelu_fast(acc[mt][nt][2 * half + 1] + b1e[c + 1]);
                *(uint32_t*)(hrow + c) = pack_h2(v0, v1);
            }
        }
    }
}

// ============ GEMM 2 (split-K=2): out += gate * (g_h @ w2h + b2) ==============
// Last CTA writes balance loss AND resets counters for the next graph replay.
__global__ __launch_bounds__(256, 2) void gemm2_kernel(
    const float* __restrict__ b2, float* __restrict__ out)
{
    const int e = blockIdx.z >> 1;
    const int ksl = blockIdx.z & 1;
    const int cnt = g_cnt[e];
    const int m0 = blockIdx.y * 128;
    const int n0 = blockIdx.x * 128;
    const int tid = threadIdx.x;
    const int total = gridDim.x * gridDim.y * gridDim.z;

    extern __shared__ char smem[];

    if (m0 < cnt) {
        const uint32_t sA = smem_u32(smem);
        const uint32_t sB = sA + NSTAGE * ABUF_H * 2;

        const int arow = tid >> 3;
        const int acol = (tid & 7) * 8;
        const __half* ap[4];
        uint32_t ab[4];
        #pragma unroll
        for (int i = 0; i < 4; i++) {
            int m = m0 + arow + 32 * i;
            bool valid = m < cnt;
            ap[i] = g_h + ((size_t)e * NTOK + (valid ? m : m0)) * HDIM +
                    ksl * KSLICE + acol;
            ab[i] = valid ? 16u : 0u;
        }
        const int brow = tid >> 4;
        const int bcol = (tid & 15) * 8;
        const __half* bp[4];
        #pragma unroll
        for (int i = 0; i < 4; i++)
            bp[i] = g_w2h + (size_t)e * HDIM * DDIM +
                    (size_t)(ksl * KSLICE + brow + 16 * i) * DDIM + n0 + bcol;

        float acc[4][4][4];
        #pragma unroll
        for (int mt = 0; mt < 4; mt++)
            #pragma unroll
            for (int nt = 0; nt < 4; nt++)
                #pragma unroll
                for (int q = 0; q < 4; q++) acc[mt][nt][q] = 0.f;

        gemm_mainloop(sA, sB, ap[0], ap[1], ap[2], ap[3], ab[0], ab[1], ab[2], ab[3],
                      bp[0], bp[1], bp[2], bp[3], (size_t)BKH * DDIM,
                      KSLICE / BKH, acc);

        const int lane = tid & 31;
        const int warp = tid >> 5;
        const int wm64 = (warp >> 2) * 64;
        const int wn32 = (warp & 3) * 32;
        const int gr = lane >> 2, tg = lane & 3;

        const float* b2e = b2 + (size_t)e * DDIM + n0;
        const float bias_scale = (ksl == 0) ? 1.0f : 0.0f;
        #pragma unroll
        for (int mt = 0; mt < 4; mt++) {
            #pragma unroll
            for (int half = 0; half < 2; half++) {
                int m = m0 + wm64 + mt * 16 + gr + 8 * half;
                if (m >= cnt) continue;
                int token = g_tok[e * NTOK + m];
                float gate = g_gate[e * NTOK + m];
                float* orow = out + (size_t)token * DDIM + n0;
                #pragma unroll
                for (int nt = 0; nt < 4; nt++) {
                    int c = wn32 + nt * 8 + 2 * tg;
                    float v0 = acc[mt][nt][2 * half + 0] + bias_scale * b2e[c];
                    float v1 = acc[mt][nt][2 * half + 1] + bias_scale * b2e[c + 1];
                    atomicAdd(&orow[c], gate * v0);
                    atomicAdd(&orow[c + 1], gate * v1);
                }
            }
        }
    }

    // fused finish: last CTA writes loss and resets state for the next replay
    if (tid == 0) {
        int old = atomicAdd(&g_g2done, 1);
        if (old == total - 1) {
            float acc = 0.f;
            #pragma unroll
            for (int q = 0; q < NEXP; q++) acc += (float)g_cnt[q] * g_psum[q];
            out[(size_t)NTOK * DDIM] =
                0.01f * (float)NEXP * acc / ((float)NTOK * (float)NTOK);
            // reset for next graph replay (all reads of these are done)
            #pragma unroll
            for (int q = 0; q < NEXP; q++) { g_cnt[q] = 0; g_psum[q] = 0.f; }
            g_g2done = 0;
        }
    }
}

// ---------------- launch ----------------
extern "C" void kernel_launch(void* const* d_in, const int* in_sizes, int n_in,
                              void* d_out, int out_size)
{
    const float* x     = (const float*)d_in[0];
    const float* gamma = (const float*)d_in[1];
    const float* beta  = (const float*)d_in[2];
    const float* gw    = (const float*)d_in[3];
    const float* w1    = (const float*)d_in[4];
    const float* b1    = (const float*)d_in[5];
    const float* w2    = (const float*)d_in[6];
    const float* b2    = (const float*)d_in[7];
    float* out = (float*)d_out;

    cudaFuncSetAttribute(gemm1_kernel, cudaFuncAttributeMaxDynamicSharedMemorySize, SMEM_BYTES);
    cudaFuncSetAttribute(gemm2_kernel, cudaFuncAttributeMaxDynamicSharedMemorySize, SMEM_BYTES);

    prep_kernel<<<NTOK + CONVBLKS, 256>>>(x, gamma, beta, gw,
                                          (const float4*)w1,
                                          out, out + (size_t)NTOK * DDIM + 1);

    // z slice NEXP carries the w2 convert blocks
    gemm1_kernel<<<dim3(HDIM / 128, NTOK / 128, NEXP + 1), 256, SMEM_BYTES>>>(
        b1, (const float4*)w2);
    gemm2_kernel<<<dim3(DDIM / 128, NTOK / 128, NEXP * SPLITK), 256, SMEM_BYTES>>>(b2, out);
}

// round 17
// speedup vs baseline: 1.1436x; 1.0143x over previous
#include <cuda_runtime.h>
#include <cuda_fp16.h>
#include <math.h>
#include <stdint.h>

#define NTOK 4096
#define DDIM 1024
#define NEXP 8
#define HDIM 4096
#define BKH 64            // k per tile (halves)
#define CONVBLKS 1024
#define SPLITK 2
#define KSLICE (HDIM / SPLITK)

// ---------------- scratch (zero-initialized at module load) ----------------
__device__ __half g_xnh[(size_t)NTOK * DDIM];
__device__ __half g_w1h[(size_t)NEXP * DDIM * HDIM];
__device__ __half g_w2h[(size_t)NEXP * HDIM * DDIM];
__device__ __half g_h[(size_t)NEXP * NTOK * HDIM];
__device__ int    g_cnt[NEXP];
__device__ float  g_psum[NEXP];
__device__ int    g_tok[NEXP * NTOK];
__device__ float  g_gate[NEXP * NTOK];
__device__ int    g_g2done;

// ---------------- helpers ----------------
__device__ __forceinline__ uint32_t smem_u32(const void* p) {
    uint32_t a;
    asm("{ .reg .u64 t; cvta.to.shared.u64 t, %1; cvt.u32.u64 %0, t; }" : "=r"(a) : "l"(p));
    return a;
}
__device__ __forceinline__ uint32_t pack_h2(float a, float b) {
    __half2 h = __floats2half2_rn(a, b);
    return *(uint32_t*)&h;
}
// fast GELU (tanh form via sigmoid): max abs dev from exact ~3e-4
__device__ __forceinline__ float gelu_fast(float x) {
    float u = 1.5957691216f * fmaf(0.044715f * x, x * x, x);
    return __fdividef(x, 1.0f + __expf(-u));
}
// MLP=4 fp32->fp16 convert over a grid-strided range (front-batched loads)
__device__ __forceinline__ void convert_mlp4(
    const float4* __restrict__ in, uint2* __restrict__ o,
    int start, int stride, int n4)
{
    int i = start;
    // main: 4 independent loads in flight
    for (; i + 3 * stride < n4; i += 4 * stride) {
        float4 v0 = in[i];
        float4 v1 = in[i + stride];
        float4 v2 = in[i + 2 * stride];
        float4 v3 = in[i + 3 * stride];
        uint2 a, b, c, d;
        a.x = pack_h2(v0.x, v0.y); a.y = pack_h2(v0.z, v0.w);
        b.x = pack_h2(v1.x, v1.y); b.y = pack_h2(v1.z, v1.w);
        c.x = pack_h2(v2.x, v2.y); c.y = pack_h2(v2.z, v2.w);
        d.x = pack_h2(v3.x, v3.y); d.y = pack_h2(v3.z, v3.w);
        o[i] = a;
        o[i + stride] = b;
        o[i + 2 * stride] = c;
        o[i + 3 * stride] = d;
    }
    for (; i < n4; i += stride) {
        float4 v = in[i];
        uint2 w;
        w.x = pack_h2(v.x, v.y);
        w.y = pack_h2(v.z, v.w);
        o[i] = w;
    }
}
// .cg: L2-only path (no L1 fill) — GEMM tiles have no L1 reuse
#define CP16(dst, src) \
    asm volatile("cp.async.cg.shared.global [%0], [%1], 16;" :: "r"(dst), "l"(src))
#define CP16Z(dst, src, bytes) \
    asm volatile("cp.async.cg.shared.global [%0], [%1], 16, %2;" :: "r"(dst), "l"(src), "r"(bytes))
#define CP_COMMIT() asm volatile("cp.async.commit_group;" ::: "memory")
#define CP_WAIT1()  asm volatile("cp.async.wait_group 1;" ::: "memory")

#define LDSM_X4(r0, r1, r2, r3, addr) \
    asm volatile("ldmatrix.sync.aligned.m8n8.x4.shared.b16 {%0,%1,%2,%3}, [%4];" \
        : "=r"(r0), "=r"(r1), "=r"(r2), "=r"(r3) : "r"(addr))
#define LDSM_X4T(r0, r1, r2, r3, addr) \
    asm volatile("ldmatrix.sync.aligned.m8n8.x4.trans.shared.b16 {%0,%1,%2,%3}, [%4];" \
        : "=r"(r0), "=r"(r1), "=r"(r2), "=r"(r3) : "r"(addr))

__device__ __forceinline__ void mma_f16(float* d, const uint32_t* a, const uint32_t* b) {
    asm volatile(
        "mma.sync.aligned.m16n8k16.row.col.f32.f16.f16.f32 "
        "{%0,%1,%2,%3}, {%4,%5,%6,%7}, {%8,%9}, {%0,%1,%2,%3};"
        : "+f"(d[0]), "+f"(d[1]), "+f"(d[2]), "+f"(d[3])
        : "r"(a[0]), "r"(a[1]), "r"(a[2]), "r"(a[3]), "r"(b[0]), "r"(b[1]));
}

// smem strides in halves (stride mod 128B = 16B -> conflict-free ldmatrix)
#define AST 72
#define BST 136
#define ABUF_H (128 * AST)
#define BBUF_H (BKH * BST)
#define NSTAGE 3
#define SMEM_BYTES ((NSTAGE * (ABUF_H + BBUF_H)) * 2 + 1024 + 128)

// ---------------- merged prep: w1 convert FIRST (long pole), then LN+router ----
__global__ __launch_bounds__(256) void prep_kernel(
    const float* __restrict__ x, const float* __restrict__ gamma,
    const float* __restrict__ beta, const float* __restrict__ gw,
    const float4* __restrict__ w1,
    float* __restrict__ out, float* __restrict__ probs_out)
{
    const int tid = threadIdx.x;

    if (blockIdx.x < CONVBLKS) {
        const int n4 = NEXP * DDIM * HDIM / 4;
        convert_mlp4(w1, (uint2*)g_w1h,
                     blockIdx.x * 256 + tid, CONVBLKS * 256, n4);
        return;
    }

    const int n = blockIdx.x - CONVBLKS;
    const int lane = tid & 31, warp = tid >> 5;

    float4 v = reinterpret_cast<const float4*>(x + (size_t)n * DDIM)[tid];
    // residual base: out = x
    reinterpret_cast<float4*>(out + (size_t)n * DDIM)[tid] = v;

    float s  = v.x + v.y + v.z + v.w;
    float ss = v.x * v.x + v.y * v.y + v.z * v.z + v.w * v.w;

    __shared__ float rs[8], rss[8];
    #pragma unroll
    for (int o = 16; o; o >>= 1) {
        s  += __shfl_down_sync(0xffffffffu, s, o);
        ss += __shfl_down_sync(0xffffffffu, ss, o);
    }
    if (lane == 0) { rs[warp] = s; rss[warp] = ss; }
    __syncthreads();

    __shared__ float s_mu, s_rstd;
    if (tid == 0) {
        float S = 0.f, SS = 0.f;
        #pragma unroll
        for (int i = 0; i < 8; i++) { S += rs[i]; SS += rss[i]; }
        float mu = S / (float)DDIM;
        float var = SS / (float)DDIM - mu * mu;
        s_mu = mu; s_rstd = rsqrtf(var + 1e-5f);
    }
    __syncthreads();
    const float mu = s_mu, r = s_rstd;

    float4 g4 = reinterpret_cast<const float4*>(gamma)[tid];
    float4 b4 = reinterpret_cast<const float4*>(beta)[tid];
    float xn0 = (v.x - mu) * r * g4.x + b4.x;
    float xn1 = (v.y - mu) * r * g4.y + b4.y;
    float xn2 = (v.z - mu) * r * g4.z + b4.z;
    float xn3 = (v.w - mu) * r * g4.w + b4.w;
    {
        uint2 o;
        o.x = pack_h2(xn0, xn1);
        o.y = pack_h2(xn2, xn3);
        reinterpret_cast<uint2*>(g_xnh + (size_t)n * DDIM)[tid] = o;
    }

    float lg[NEXP];
    {
        const float4* gwr = reinterpret_cast<const float4*>(gw + (size_t)tid * 4 * NEXP);
        float4 a0 = gwr[0], a1 = gwr[1];
        float4 c0 = gwr[2], c1 = gwr[3];
        float4 d0 = gwr[4], d1 = gwr[5];
        float4 e0 = gwr[6], e1 = gwr[7];
        lg[0] = xn0*a0.x + xn1*c0.x + xn2*d0.x + xn3*e0.x;
        lg[1] = xn0*a0.y + xn1*c0.y + xn2*d0.y + xn3*e0.y;
        lg[2] = xn0*a0.z + xn1*c0.z + xn2*d0.z + xn3*e0.z;
        lg[3] = xn0*a0.w + xn1*c0.w + xn2*d0.w + xn3*e0.w;
        lg[4] = xn0*a1.x + xn1*c1.x + xn2*d1.x + xn3*e1.x;
        lg[5] = xn0*a1.y + xn1*c1.y + xn2*d1.y + xn3*e1.y;
        lg[6] = xn0*a1.z + xn1*c1.z + xn2*d1.z + xn3*e1.z;
        lg[7] = xn0*a1.w + xn1*c1.w + xn2*d1.w + xn3*e1.w;
    }

    __shared__ float sl[8][NEXP];
    #pragma unroll
    for (int e = 0; e < NEXP; e++) {
        float t = lg[e];
        #pragma unroll
        for (int o = 16; o; o >>= 1) t += __shfl_down_sync(0xffffffffu, t, o);
        if (lane == 0) sl[warp][e] = t;
    }
    __syncthreads();

    if (tid == 0) {
        float logit[NEXP];
        #pragma unroll
        for (int e = 0; e < NEXP; e++) {
            float t = 0.f;
            #pragma unroll
            for (int w = 0; w < 8; w++) t += sl[w][e];
            logit[e] = t;
        }
        float mx = logit[0];
        #pragma unroll
        for (int e = 1; e < NEXP; e++) mx = fmaxf(mx, logit[e]);
        float p[NEXP], denom = 0.f;
        #pragma unroll
        for (int e = 0; e < NEXP; e++) { p[e] = expf(logit[e] - mx); denom += p[e]; }
        float inv = 1.0f / denom;
        #pragma unroll
        for (int e = 0; e < NEXP; e++) {
            p[e] *= inv;
            probs_out[(size_t)n * NEXP + e] = p[e];
            atomicAdd(&g_psum[e], p[e]);
        }
        int i1 = 0;
        #pragma unroll
        for (int e = 1; e < NEXP; e++) if (p[e] > p[i1]) i1 = e;
        int i2 = (i1 == 0) ? 1 : 0;
        #pragma unroll
        for (int e = 0; e < NEXP; e++) if (e != i1 && p[e] > p[i2]) i2 = e;
        float wsum = p[i1] + p[i2] + 1e-8f;
        float w1v = p[i1] / wsum, w2v = p[i2] / wsum;
        int r1 = atomicAdd(&g_cnt[i1], 1);
        g_tok[i1 * NTOK + r1] = n; g_gate[i1 * NTOK + r1] = w1v;
        int r2 = atomicAdd(&g_cnt[i2], 1);
        g_tok[i2 * NTOK + r2] = n; g_gate[i2 * NTOK + r2] = w2v;
    }
}

// ============ fp16 HMMA GEMM core: BM=128,BN=128,BK=64, 256 threads ============
__device__ __forceinline__ void gemm_mainloop(
    uint32_t sA, uint32_t sB,
    const __half* aptr0, const __half* aptr1, const __half* aptr2, const __half* aptr3,
    uint32_t ab0, uint32_t ab1, uint32_t ab2, uint32_t ab3,
    const __half* bptr0, const __half* bptr1, const __half* bptr2, const __half* bptr3,
    size_t b_adv,
    int NK, float acc[4][4][4])
{
    const int tid = threadIdx.x;
    const int lane = tid & 31;
    const int warp = tid >> 5;
    const int wm64 = (warp >> 2) * 64;
    const int wn32 = (warp & 3) * 32;

    const uint32_t a_soff = (uint32_t)(((tid >> 3) * AST + (tid & 7) * 8) * 2);
    const uint32_t b_soff = (uint32_t)(((tid >> 4) * BST + (tid & 15) * 8) * 2);
    const uint32_t a_rstep = (uint32_t)(32 * AST * 2);
    const uint32_t b_rstep = (uint32_t)(16 * BST * 2);

    const int lrow = (lane & 7) + 8 * ((lane >> 3) & 1);
    const int lhi  = 8 * (lane >> 4);
    uint32_t aoff[4], boff[2];
    #pragma unroll
    for (int mt = 0; mt < 4; mt++)
        aoff[mt] = (uint32_t)(((wm64 + mt * 16 + lrow) * AST + lhi) * 2);
    #pragma unroll
    for (int np = 0; np < 2; np++)
        boff[np] = (uint32_t)((lrow * BST + wn32 + np * 16 + lhi) * 2);

    const __half* ap[4] = {aptr0, aptr1, aptr2, aptr3};
    uint32_t ab[4] = {ab0, ab1, ab2, ab3};
    const __half* bp[4] = {bptr0, bptr1, bptr2, bptr3};

    #pragma unroll
    for (int st = 0; st < 2; st++) {
        uint32_t dA = sA + st * (ABUF_H * 2) + a_soff;
        uint32_t dB = sB + st * (BBUF_H * 2) + b_soff;
        #pragma unroll
        for (int i = 0; i < 4; i++) {
            CP16Z(dA + i * a_rstep, ap[i], ab[i]); ap[i] += BKH;
        }
        #pragma unroll
        for (int i = 0; i < 4; i++) {
            CP16(dB + i * b_rstep, bp[i]); bp[i] += b_adv;
        }
        CP_COMMIT();
    }

    for (int ic = 0; ic < NK; ic++) {
        CP_WAIT1();
        __syncthreads();

        if (ic + 2 < NK) {
            const int st = (ic + 2) % NSTAGE;
            uint32_t dA = sA + st * (ABUF_H * 2) + a_soff;
            uint32_t dB = sB + st * (BBUF_H * 2) + b_soff;
            #pragma unroll
            for (int i = 0; i < 4; i++) {
                CP16Z(dA + i * a_rstep, ap[i], ab[i]); ap[i] += BKH;
            }
            #pragma unroll
            for (int i = 0; i < 4; i++) {
                CP16(dB + i * b_rstep, bp[i]); bp[i] += b_adv;
            }
        }
        CP_COMMIT();

        const uint32_t sAt = sA + (ic % NSTAGE) * (ABUF_H * 2);
        const uint32_t sBt = sB + (ic % NSTAGE) * (BBUF_H * 2);
        #pragma unroll
        for (int ks = 0; ks < 4; ks++) {
            uint32_t af[4][4], bf[2][4];
            #pragma unroll
            for (int mt = 0; mt < 4; mt++)
                LDSM_X4(af[mt][0], af[mt][1], af[mt][2], af[mt][3],
                        sAt + aoff[mt] + ks * 32);
            #pragma unroll
            for (int np = 0; np < 2; np++)
                LDSM_X4T(bf[np][0], bf[np][1], bf[np][2], bf[np][3],
                         sBt + boff[np] + ks * 16 * BST * 2);
            #pragma unroll
            for (int mt = 0; mt < 4; mt++)
                #pragma unroll
                for (int nt = 0; nt < 4; nt++)
                    mma_f16(acc[mt][nt], af[mt], &bf[nt >> 1][(nt & 1) * 2]);
        }
    }
}

// ============ GEMM 1: g_h = gelu(gather(g_xnh) @ w1h + b1)  (+ w2 convert) ====
__global__ __launch_bounds__(256, 2) void gemm1_kernel(
    const float* __restrict__ b1, const float4* __restrict__ w2)
{
    const int tid = threadIdx.x;

    if (blockIdx.z == NEXP) {
        const int n4 = NEXP * HDIM * DDIM / 4;
        const int nblk = gridDim.x * gridDim.y;
        const int bid = blockIdx.y * gridDim.x + blockIdx.x;
        convert_mlp4(w2, (uint2*)g_w2h, bid * 256 + tid, nblk * 256, n4);
        return;
    }

    const int e = blockIdx.z;
    const int cnt = g_cnt[e];
    const int m0 = blockIdx.y * 128;
    if (m0 >= cnt) return;
    const int n0 = blockIdx.x * 128;

    extern __shared__ char smem[];
    const uint32_t sA = smem_u32(smem);
    const uint32_t sB = sA + NSTAGE * ABUF_H * 2;
    int* s_tok = (int*)(smem + NSTAGE * (ABUF_H + BBUF_H) * 2);

    if (tid < 128)
        s_tok[tid] = (m0 + tid < cnt) ? g_tok[e * NTOK + m0 + tid] : 0;
    __syncthreads();

    const int arow = tid >> 3;
    const int acol = (tid & 7) * 8;
    const __half* ap[4];
    uint32_t ab[4];
    #pragma unroll
    for (int i = 0; i < 4; i++) {
        int m = m0 + arow + 32 * i;
        bool valid = m < cnt;
        ap[i] = g_xnh + (size_t)s_tok[arow + 32 * i] * DDIM + acol;
        ab[i] = valid ? 16u : 0u;
    }
    const int brow = tid >> 4;
    const int bcol = (tid & 15) * 8;
    const __half* bp[4];
    #pragma unroll
    for (int i = 0; i < 4; i++)
        bp[i] = g_w1h + (size_t)e * DDIM * HDIM + (size_t)(brow + 16 * i) * HDIM + n0 + bcol;

    float acc[4][4][4];
    #pragma unroll
    for (int mt = 0; mt < 4; mt++)
        #pragma unroll
        for (int nt = 0; nt < 4; nt++)
            #pragma unroll
            for (int q = 0; q < 4; q++) acc[mt][nt][q] = 0.f;

    gemm_mainloop(sA, sB, ap[0], ap[1], ap[2], ap[3], ab[0], ab[1], ab[2], ab[3],
                  bp[0], bp[1], bp[2], bp[3], (size_t)BKH * HDIM,
                  DDIM / BKH, acc);

    const int lane = tid & 31;
    const int warp = tid >> 5;
    const int wm64 = (warp >> 2) * 64;
    const int wn32 = (warp & 3) * 32;
    const int gr = lane >> 2, tg = lane & 3;

    const float* b1e = b1 + (size_t)e * HDIM + n0;
    #pragma unroll
    for (int mt = 0; mt < 4; mt++) {
        #pragma unroll
        for (int half = 0; half < 2; half++) {
            int m = m0 + wm64 + mt * 16 + gr + 8 * half;
            if (m >= cnt) continue;
            __half* hrow = g_h + ((size_t)e * NTOK + m) * HDIM + n0;
            #pragma unroll
            for (int nt = 0; nt < 4; nt++) {
                int c = wn32 + nt * 8 + 2 * tg;
                float v0 = gelu_fast(acc[mt][nt][2 * half + 0] + b1e[c]);
                float v1 = gelu_fast(acc[mt][nt][2 * half + 1] + b1e[c + 1]);
                *(uint32_t*)(hrow + c) = pack_h2(v0, v1);
            }
        }
    }
}

// ============ GEMM 2 (split-K=2): out += gate * (g_h @ w2h + b2) ==============
// Last CTA writes balance loss AND resets counters for the next graph replay.
__global__ __launch_bounds__(256, 2) void gemm2_kernel(
    const float* __restrict__ b2, float* __restrict__ out)
{
    const int e = blockIdx.z >> 1;
    const int ksl = blockIdx.z & 1;
    const int cnt = g_cnt[e];
    const int m0 = blockIdx.y * 128;
    const int n0 = blockIdx.x * 128;
    const int tid = threadIdx.x;
    const int total = gridDim.x * gridDim.y * gridDim.z;

    extern __shared__ char smem[];

    if (m0 < cnt) {
        const uint32_t sA = smem_u32(smem);
        const uint32_t sB = sA + NSTAGE * ABUF_H * 2;

        const int arow = tid >> 3;
        const int acol = (tid & 7) * 8;
        const __half* ap[4];
        uint32_t ab[4];
        #pragma unroll
        for (int i = 0; i < 4; i++) {
            int m = m0 + arow + 32 * i;
            bool valid = m < cnt;
            ap[i] = g_h + ((size_t)e * NTOK + (valid ? m : m0)) * HDIM +
                    ksl * KSLICE + acol;
            ab[i] = valid ? 16u : 0u;
        }
        const int brow = tid >> 4;
        const int bcol = (tid & 15) * 8;
        const __half* bp[4];
        #pragma unroll
        for (int i = 0; i < 4; i++)
            bp[i] = g_w2h + (size_t)e * HDIM * DDIM +
                    (size_t)(ksl * KSLICE + brow + 16 * i) * DDIM + n0 + bcol;

        float acc[4][4][4];
        #pragma unroll
        for (int mt = 0; mt < 4; mt++)
            #pragma unroll
            for (int nt = 0; nt < 4; nt++)
                #pragma unroll
                for (int q = 0; q < 4; q++) acc[mt][nt][q] = 0.f;

        gemm_mainloop(sA, sB, ap[0], ap[1], ap[2], ap[3], ab[0], ab[1], ab[2], ab[3],
                      bp[0], bp[1], bp[2], bp[3], (size_t)BKH * DDIM,
                      KSLICE / BKH, acc);

        const int lane = tid & 31;
        const int warp = tid >> 5;
        const int wm64 = (warp >> 2) * 64;
        const int wn32 = (warp & 3) * 32;
        const int gr = lane >> 2, tg = lane & 3;

        const float* b2e = b2 + (size_t)e * DDIM + n0;
        const float bias_scale = (ksl == 0) ? 1.0f : 0.0f;
        #pragma unroll
        for (int mt = 0; mt < 4; mt++) {
            #pragma unroll
            for (int half = 0; half < 2; half++) {
                int m = m0 + wm64 + mt * 16 + gr + 8 * half;
                if (m >= cnt) continue;
                int token = g_tok[e * NTOK + m];
                float gate = g_gate[e * NTOK + m];
                float* orow = out + (size_t)token * DDIM + n0;
                #pragma unroll
                for (int nt = 0; nt < 4; nt++) {
                    int c = wn32 + nt * 8 + 2 * tg;
                    float v0 = acc[mt][nt][2 * half + 0] + bias_scale * b2e[c];
                    float v1 = acc[mt][nt][2 * half + 1] + bias_scale * b2e[c + 1];
                    atomicAdd(&orow[c], gate * v0);
                    atomicAdd(&orow[c + 1], gate * v1);
                }
            }
        }
    }

    // fused finish: last CTA writes loss and resets state for the next replay
    if (tid == 0) {
        int old = atomicAdd(&g_g2done, 1);
        if (old == total - 1) {
            float acc = 0.f;
            #pragma unroll
            for (int q = 0; q < NEXP; q++) acc += (float)g_cnt[q] * g_psum[q];
            out[(size_t)NTOK * DDIM] =
                0.01f * (float)NEXP * acc / ((float)NTOK * (float)NTOK);
            #pragma unroll
            for (int q = 0; q < NEXP; q++) { g_cnt[q] = 0; g_psum[q] = 0.f; }
            g_g2done = 0;
        }
    }
}

// ---------------- launch ----------------
extern "C" void kernel_launch(void* const* d_in, const int* in_sizes, int n_in,
                              void* d_out, int out_size)
{
    const float* x     = (const float*)d_in[0];
    const float* gamma = (const float*)d_in[1];
    const float* beta  = (const float*)d_in[2];
    const float* gw    = (const float*)d_in[3];
    const float* w1    = (const float*)d_in[4];
    const float* w2    = (const float*)d_in[6];
    const float* b1    = (const float*)d_in[5];
    const float* b2    = (const float*)d_in[7];
    float* out = (float*)d_out;

    cudaFuncSetAttribute(gemm1_kernel, cudaFuncAttributeMaxDynamicSharedMemorySize, SMEM_BYTES);
    cudaFuncSetAttribute(gemm2_kernel, cudaFuncAttributeMaxDynamicSharedMemorySize, SMEM_BYTES);

    prep_kernel<<<NTOK + CONVBLKS, 256>>>(x, gamma, beta, gw,
                                          (const float4*)w1,
                                          out, out + (size_t)NTOK * DDIM + 1);

    // z slice NEXP carries the w2 convert blocks
    gemm1_kernel<<<dim3(HDIM / 128, NTOK / 128, NEXP + 1), 256, SMEM_BYTES>>>(
        b1, (const float4*)w2);
    gemm2_kernel<<<dim3(DDIM / 128, NTOK / 128, NEXP * SPLITK), 256, SMEM_BYTES>>>(b2, out);
}